// round 3
// baseline (speedup 1.0000x reference)
#include <cuda_runtime.h>

#define T_ 4
#define B_ 16
#define C_ 256
#define N_ 1024
#define CN_ (C_*N_)          // 262144
#define BCN (B_*C_*N_)       // 4194304
#define TBCN (T_*BCN)        // 16777216
#define NBITS (T_*B_*8*N_)   // 524288 words per branch

// Scratch (device globals: allocation-free)
__device__ float    g_y[3][TBCN];     // post-BN pre-LIF activations for q,k,v
__device__ unsigned g_bits[3][NBITS]; // spike bitpack: word at ((t*B+b)*8+h)*N+n, bit d=c%32
__device__ float    g_xa[TBCN];       // attention output (pre-LIF2)
__device__ float    g_xs[TBCN];       // LIF2 spikes (float, input to p-GEMM)
__device__ float    g_yp[TBCN];       // p-GEMM post-BN (pre-LIF3)

// ---------------------------------------------------------------------------
// GEMM + BN:  Y[tb, o, n] = BN( sum_c W[o,c] * X[tb, c, n] + bias[o] )
// Tile: 128x128x8, 256 threads, 8x8 per-thread register tile.
// Inner product uses packed fp32x2 FMA (exact fp32, 2 lanes / instruction).
// A smem tile is stored DUPLICATED (As2[k][2m]=As2[k][2m+1]=a[m]) so packed
// A operands load directly via LDS.128 with no splat MOVs.
// ---------------------------------------------------------------------------
__global__ __launch_bounds__(256, 2)
void gemm_bn_kernel(const float* __restrict__ Xin, int use_gxs, int ydst,
                    const float* __restrict__ W,
                    const float* __restrict__ bias,
                    const float* __restrict__ gamma,
                    const float* __restrict__ beta,
                    const float* __restrict__ mean,
                    const float* __restrict__ var)
{
    __shared__ __align__(16) float As2[8][256];
    __shared__ __align__(16) float Bs[8][128];

    const float* X = use_gxs ? g_xs : Xin;
    float* Y = (ydst < 3) ? g_y[ydst] : g_yp;

    const int tb = blockIdx.z;
    const int m0 = blockIdx.y * 128;
    const int n0 = blockIdx.x * 128;
    const float* Xb = X + (size_t)tb * CN_;
    float* Yb = Y + (size_t)tb * CN_;
    const int tid = threadIdx.x;

    const int la_m = tid >> 1;          // 0..127
    const int la_k = (tid & 1) * 4;     // 0 or 4
    const int lb_k = tid >> 5;          // 0..7
    const int lb_n = (tid & 31) * 4;    // 0..124

    const int tx = tid & 15;            // n-group (8 n per thread = 4 pairs)
    const int ty = tid >> 4;            // m-group (8 m per thread)

    // acc[i][j]: packed pair (n=2j, n=2j+1) for output row i. Zero-init = {0f,0f}.
    unsigned long long acc[8][4] = {};

    for (int k0 = 0; k0 < C_; k0 += 8) {
        float4 a4 = *(const float4*)(W + (size_t)(m0 + la_m) * C_ + k0 + la_k);
        *(float2*)&As2[la_k + 0][2 * la_m] = make_float2(a4.x, a4.x);
        *(float2*)&As2[la_k + 1][2 * la_m] = make_float2(a4.y, a4.y);
        *(float2*)&As2[la_k + 2][2 * la_m] = make_float2(a4.z, a4.z);
        *(float2*)&As2[la_k + 3][2 * la_m] = make_float2(a4.w, a4.w);
        *(float4*)&Bs[lb_k][lb_n] =
            *(const float4*)(Xb + (size_t)(k0 + lb_k) * N_ + n0 + lb_n);
        __syncthreads();
        #pragma unroll
        for (int k = 0; k < 8; k++) {
            ulonglong2 a01 = *(const ulonglong2*)&As2[k][ty * 16 + 0];
            ulonglong2 a23 = *(const ulonglong2*)&As2[k][ty * 16 + 4];
            ulonglong2 a45 = *(const ulonglong2*)&As2[k][ty * 16 + 8];
            ulonglong2 a67 = *(const ulonglong2*)&As2[k][ty * 16 + 12];
            ulonglong2 bp0 = *(const ulonglong2*)&Bs[k][tx * 8 + 0];
            ulonglong2 bp1 = *(const ulonglong2*)&Bs[k][tx * 8 + 4];
            unsigned long long a2[8] = {a01.x, a01.y, a23.x, a23.y,
                                        a45.x, a45.y, a67.x, a67.y};
            unsigned long long b2[4] = {bp0.x, bp0.y, bp1.x, bp1.y};
            #pragma unroll
            for (int i = 0; i < 8; i++)
                #pragma unroll
                for (int j = 0; j < 4; j++)
                    asm("fma.rn.f32x2 %0, %1, %2, %0;"
                        : "+l"(acc[i][j]) : "l"(a2[i]), "l"(b2[j]));
        }
        __syncthreads();
    }

    #pragma unroll
    for (int i = 0; i < 8; i++) {
        int o = m0 + ty * 8 + i;
        float sc = gamma[o] * rsqrtf(var[o] + 1e-5f);
        float sh = beta[o] - mean[o] * sc;
        float bi = bias ? bias[o] : 0.f;
        float f[8];
        #pragma unroll
        for (int j = 0; j < 4; j++)
            asm("mov.b64 {%0, %1}, %2;"
                : "=f"(f[2 * j]), "=f"(f[2 * j + 1]) : "l"(acc[i][j]));
        float* yr = Yb + (size_t)o * N_ + n0 + tx * 8;
        float4 v0 = make_float4((f[0] + bi) * sc + sh, (f[1] + bi) * sc + sh,
                                (f[2] + bi) * sc + sh, (f[3] + bi) * sc + sh);
        float4 v1 = make_float4((f[4] + bi) * sc + sh, (f[5] + bi) * sc + sh,
                                (f[6] + bi) * sc + sh, (f[7] + bi) * sc + sh);
        *(float4*)yr = v0;
        *(float4*)(yr + 4) = v1;
    }
}

// ---------------------------------------------------------------------------
// LIF over T (vth=1) for q,k,v + bitpack: bit d of word (t,b,h,n) = spike of
// channel c=h*32+d at spatial n. One thread per (b,h,n), loops d and t.
// ---------------------------------------------------------------------------
__global__ __launch_bounds__(256)
void lif_pack_kernel()
{
    const int proj = blockIdx.y;
    const int idx = blockIdx.x * 256 + threadIdx.x;  // < B*8*N = 131072
    const int n = idx & (N_ - 1);
    const int h = (idx >> 10) & 7;
    const int b = idx >> 13;
    const float* Y = g_y[proj];

    unsigned bits[4] = {0u, 0u, 0u, 0u};
    for (int d = 0; d < 32; d++) {
        const float* p = Y + (size_t)b * CN_ + (size_t)(h * 32 + d) * N_ + n;
        float mem = 0.f;
        #pragma unroll
        for (int t = 0; t < 4; t++) {
            float y = p[(size_t)t * BCN];
            mem += (y - mem) * 0.5f;
            if (mem >= 1.0f) { bits[t] |= (1u << d); mem = 0.f; }
        }
    }
    const int ob = (b * 8 + h) * N_ + n;
    #pragma unroll
    for (int t = 0; t < 4; t++)
        g_bits[proj][t * (B_ * 8 * N_) + ob] = bits[t];
}

// ---------------------------------------------------------------------------
// Write v output: v[t,b,h,n,e] = spike bit e of word (t,b,h,n). Linear idx
// over [T,B,h,N,d] (d fastest) -> word = idx>>5, bit = idx&31. Coalesced.
// ---------------------------------------------------------------------------
__global__ __launch_bounds__(256)
void v_writer_kernel(float* __restrict__ vout)
{
    const int idx = blockIdx.x * 256 + threadIdx.x;
    unsigned w = g_bits[2][idx >> 5];
    vout[idx] = (float)((w >> (idx & 31)) & 1u);
}

// ---------------------------------------------------------------------------
// Per (t,b,h): kv[d][e] = popc-sum over n of k_d(n)&v_e(n); then
// xa[c=h*32+e][n] = 0.125 * sum_d q_d(n) * kv[d][e].
// ---------------------------------------------------------------------------
__global__ __launch_bounds__(256)
void kv_attn_kernel()
{
    __shared__ unsigned qb[1024], kb[1024], vb[1024];
    __shared__ unsigned krow[32][33], vrow[32][33];
    __shared__ float kvm[32][33];

    const int bid = blockIdx.x;    // (t*B+b)*8+h
    const int tid = threadIdx.x;
    const unsigned base = (unsigned)bid * 1024u;

    for (int i = tid; i < 1024; i += 256) {
        qb[i] = g_bits[0][base + i];
        kb[i] = g_bits[1][base + i];
        vb[i] = g_bits[2][base + i];
    }
    __syncthreads();

    // bit-transpose k,v: krow[d][w] has bit j = spike(channel d, n=w*32+j)
    const int d = tid & 31;
    for (int w = tid >> 5; w < 32; w += 8) {
        unsigned rk = 0u, rv = 0u;
        #pragma unroll
        for (int j = 0; j < 32; j++) {
            rk |= ((kb[w * 32 + j] >> d) & 1u) << j;
            rv |= ((vb[w * 32 + j] >> d) & 1u) << j;
        }
        krow[d][w] = rk; vrow[d][w] = rv;
    }
    __syncthreads();

    for (int p = tid; p < 1024; p += 256) {
        int dd = p >> 5, e = p & 31;
        int s = 0;
        #pragma unroll
        for (int w = 0; w < 32; w++)
            s += __popc(krow[dd][w] & vrow[e][w]);
        kvm[dd][e] = (float)s;
    }
    __syncthreads();

    const int tb = bid >> 3, h = bid & 7;
    const int nl = tid & 31;
    for (int e = tid >> 5; e < 32; e += 8) {
        float* out = g_xa + (size_t)tb * CN_ + (size_t)(h * 32 + e) * N_;
        for (int j = 0; j < 32; j++) {
            int n = nl + j * 32;
            unsigned qm = qb[n];
            float s = 0.f;
            if (qm) {
                #pragma unroll
                for (int dd = 0; dd < 32; dd++)
                    if (qm & (1u << dd)) s += kvm[dd][e];
            }
            out[n] = 0.125f * s;
        }
    }
}

// ---------------------------------------------------------------------------
// Generic float LIF over T. src: 0 -> g_xa, 1 -> g_yp. dst: g_xs or out ptr.
// ---------------------------------------------------------------------------
__global__ __launch_bounds__(256)
void lif_f_kernel(int src_sel, float* __restrict__ dst_ptr, int dst_is_ptr, float vth)
{
    const int idx = blockIdx.x * 256 + threadIdx.x;   // < BCN
    const float* Y = src_sel ? g_yp : g_xa;
    float* S = dst_is_ptr ? dst_ptr : g_xs;
    float mem = 0.f;
    #pragma unroll
    for (int t = 0; t < 4; t++) {
        float y = Y[(size_t)t * BCN + idx];
        mem += (y - mem) * 0.5f;
        float s = (mem >= vth) ? 1.0f : 0.0f;
        S[(size_t)t * BCN + idx] = s;
        mem *= (1.0f - s);
    }
}

// ---------------------------------------------------------------------------
extern "C" void kernel_launch(void* const* d_in, const int* in_sizes, int n_in,
                              void* d_out, int out_size)
{
    const float* x  = (const float*)d_in[0];
    // inputs: x, res_attn, {q,k,v}x{w,gamma,beta,mean,var}, p_{w,b,gamma,beta,mean,var}
    const float* qw = (const float*)d_in[2];
    const float* qg = (const float*)d_in[3];
    const float* qb = (const float*)d_in[4];
    const float* qm = (const float*)d_in[5];
    const float* qv = (const float*)d_in[6];
    const float* kw = (const float*)d_in[7];
    const float* kg = (const float*)d_in[8];
    const float* kb = (const float*)d_in[9];
    const float* km = (const float*)d_in[10];
    const float* kv = (const float*)d_in[11];
    const float* vw = (const float*)d_in[12];
    const float* vg = (const float*)d_in[13];
    const float* vb = (const float*)d_in[14];
    const float* vm = (const float*)d_in[15];
    const float* vv = (const float*)d_in[16];
    const float* pw = (const float*)d_in[17];
    const float* pb = (const float*)d_in[18];
    const float* pg = (const float*)d_in[19];
    const float* pbt = (const float*)d_in[20];
    const float* pm = (const float*)d_in[21];
    const float* pv = (const float*)d_in[22];

    float* out  = (float*)d_out;
    float* vout = out + TBCN;

    dim3 ggrid(N_ / 128, C_ / 128, T_ * B_);
    // q, k, v projections -> g_y[0..2]
    gemm_bn_kernel<<<ggrid, 256>>>(x, 0, 0, qw, nullptr, qg, qb, qm, qv);
    gemm_bn_kernel<<<ggrid, 256>>>(x, 0, 1, kw, nullptr, kg, kb, km, kv);
    gemm_bn_kernel<<<ggrid, 256>>>(x, 0, 2, vw, nullptr, vg, vb, vm, vv);

    // LIF + bitpack for all three branches
    lif_pack_kernel<<<dim3((B_ * 8 * N_) / 256, 3), 256>>>();

    // v output
    if (out_size >= 2 * TBCN)
        v_writer_kernel<<<TBCN / 256, 256>>>(vout);

    // kv + attn -> g_xa
    kv_attn_kernel<<<T_ * B_ * 8, 256>>>();

    // LIF(0.5) -> g_xs
    lif_f_kernel<<<BCN / 256, 256>>>(0, nullptr, 0, 0.5f);

    // p projection + bias + BN -> g_yp
    gemm_bn_kernel<<<ggrid, 256>>>(nullptr, 1, 3, pw, pb, pg, pbt, pm, pv);

    // LIF(1.0) -> out
    lif_f_kernel<<<BCN / 256, 256>>>(1, out, 1, 1.0f);
}

// round 4
// speedup vs baseline: 1.3761x; 1.3761x over previous
#include <cuda_runtime.h>

#define T_ 4
#define B_ 16
#define C_ 256
#define N_ 1024
#define CN_ (C_*N_)          // 262144
#define BCN (B_*C_*N_)       // 4194304
#define TBCN (T_*BCN)        // 16777216
#define NBITS (T_*B_*8*N_)   // 524288 words per branch

// Scratch (device globals: allocation-free)
__device__ float    g_y[3][TBCN];     // post-BN pre-LIF activations for q,k,v
__device__ unsigned g_bits[4][NBITS]; // spike bitpacks: q,k,v, xs
__device__ float    g_xa[TBCN];       // attention output (pre-LIF2)
__device__ float    g_wt[C_*C_];      // p_w transposed: g_wt[c*256+o] = pw[o*256+c]

// ---------------------------------------------------------------------------
// GEMM + BN:  Y[tb, o, n] = BN( sum_c W[o,c] * X[tb, c, n] )
// Tile: 128x128x8, 256 threads, 8x8 per-thread register tile. (scalar FFMA —
// measured at the fp32 issue roofline; f32x2 variant regressed, reverted)
// ---------------------------------------------------------------------------
__global__ __launch_bounds__(256, 2)
void gemm_bn_kernel(const float* __restrict__ X, int ydst,
                    const float* __restrict__ W,
                    const float* __restrict__ gamma,
                    const float* __restrict__ beta,
                    const float* __restrict__ mean,
                    const float* __restrict__ var)
{
    __shared__ float As[8][128];
    __shared__ float Bs[8][128];

    float* Y = g_y[ydst];

    const int tb = blockIdx.z;
    const int m0 = blockIdx.y * 128;
    const int n0 = blockIdx.x * 128;
    const float* Xb = X + (size_t)tb * CN_;
    float* Yb = Y + (size_t)tb * CN_;
    const int tid = threadIdx.x;

    const int la_m = tid >> 1;          // 0..127
    const int la_k = (tid & 1) * 4;     // 0 or 4
    const int lb_k = tid >> 5;          // 0..7
    const int lb_n = (tid & 31) * 4;    // 0..124

    const int tx = tid & 15;            // n-group
    const int ty = tid >> 4;            // m-group

    float acc[8][8];
    #pragma unroll
    for (int i = 0; i < 8; i++)
        #pragma unroll
        for (int j = 0; j < 8; j++) acc[i][j] = 0.f;

    for (int k0 = 0; k0 < C_; k0 += 8) {
        float4 a4 = *(const float4*)(W + (size_t)(m0 + la_m) * C_ + k0 + la_k);
        As[la_k + 0][la_m] = a4.x;
        As[la_k + 1][la_m] = a4.y;
        As[la_k + 2][la_m] = a4.z;
        As[la_k + 3][la_m] = a4.w;
        *(float4*)&Bs[lb_k][lb_n] =
            *(const float4*)(Xb + (size_t)(k0 + lb_k) * N_ + n0 + lb_n);
        __syncthreads();
        #pragma unroll
        for (int k = 0; k < 8; k++) {
            float4 a0 = *(const float4*)&As[k][ty * 8];
            float4 a1 = *(const float4*)&As[k][ty * 8 + 4];
            float4 b0 = *(const float4*)&Bs[k][tx * 8];
            float4 b1 = *(const float4*)&Bs[k][tx * 8 + 4];
            float am[8] = {a0.x, a0.y, a0.z, a0.w, a1.x, a1.y, a1.z, a1.w};
            float bn[8] = {b0.x, b0.y, b0.z, b0.w, b1.x, b1.y, b1.z, b1.w};
            #pragma unroll
            for (int i = 0; i < 8; i++)
                #pragma unroll
                for (int j = 0; j < 8; j++)
                    acc[i][j] += am[i] * bn[j];
        }
        __syncthreads();
    }

    #pragma unroll
    for (int i = 0; i < 8; i++) {
        int o = m0 + ty * 8 + i;
        float sc = gamma[o] * rsqrtf(var[o] + 1e-5f);
        float sh = beta[o] - mean[o] * sc;
        float* yr = Yb + (size_t)o * N_ + n0 + tx * 8;
        float4 v0 = make_float4(acc[i][0] * sc + sh, acc[i][1] * sc + sh,
                                acc[i][2] * sc + sh, acc[i][3] * sc + sh);
        float4 v1 = make_float4(acc[i][4] * sc + sh, acc[i][5] * sc + sh,
                                acc[i][6] * sc + sh, acc[i][7] * sc + sh);
        *(float4*)yr = v0;
        *(float4*)(yr + 4) = v1;
    }
}

// ---------------------------------------------------------------------------
// LIF over T + bitpack: bit d of word (t,b,w,n) = spike of channel c=w*32+d.
// proj = proj_base + blockIdx.y; src = g_y[proj] for proj<3, g_xa for proj==3.
// ---------------------------------------------------------------------------
__global__ __launch_bounds__(256)
void lif_pack_kernel(int proj_base, float vth)
{
    const int proj = proj_base + blockIdx.y;
    const int idx = blockIdx.x * 256 + threadIdx.x;  // < B*8*N = 131072
    const int n = idx & (N_ - 1);
    const int h = (idx >> 10) & 7;
    const int b = idx >> 13;
    const float* Y = (proj < 3) ? g_y[proj] : g_xa;

    unsigned bits[4] = {0u, 0u, 0u, 0u};
    for (int d = 0; d < 32; d++) {
        const float* p = Y + (size_t)b * CN_ + (size_t)(h * 32 + d) * N_ + n;
        float mem = 0.f;
        #pragma unroll
        for (int t = 0; t < 4; t++) {
            float y = p[(size_t)t * BCN];
            mem += (y - mem) * 0.5f;
            if (mem >= vth) { bits[t] |= (1u << d); mem = 0.f; }
        }
    }
    const int ob = (b * 8 + h) * N_ + n;
    #pragma unroll
    for (int t = 0; t < 4; t++)
        g_bits[proj][t * (B_ * 8 * N_) + ob] = bits[t];
}

// ---------------------------------------------------------------------------
// Write v output: v[t,b,h,n,e] = spike bit e of word (t,b,h,n).
// ---------------------------------------------------------------------------
__global__ __launch_bounds__(256)
void v_writer_kernel(float* __restrict__ vout)
{
    const int idx = blockIdx.x * 256 + threadIdx.x;
    unsigned w = g_bits[2][idx >> 5];
    vout[idx] = (float)((w >> (idx & 31)) & 1u);
}

// ---------------------------------------------------------------------------
// Per (t,b,h): kv[d][e] = popc over n of k_d & v_e; xa = 0.125 * q·kv.
// ---------------------------------------------------------------------------
__global__ __launch_bounds__(256)
void kv_attn_kernel()
{
    __shared__ unsigned qb[1024], kb[1024], vb[1024];
    __shared__ unsigned krow[32][33], vrow[32][33];
    __shared__ float kvm[32][33];

    const int bid = blockIdx.x;    // (t*B+b)*8+h
    const int tid = threadIdx.x;
    const unsigned base = (unsigned)bid * 1024u;

    for (int i = tid; i < 1024; i += 256) {
        qb[i] = g_bits[0][base + i];
        kb[i] = g_bits[1][base + i];
        vb[i] = g_bits[2][base + i];
    }
    __syncthreads();

    const int d = tid & 31;
    for (int w = tid >> 5; w < 32; w += 8) {
        unsigned rk = 0u, rv = 0u;
        #pragma unroll
        for (int j = 0; j < 32; j++) {
            rk |= ((kb[w * 32 + j] >> d) & 1u) << j;
            rv |= ((vb[w * 32 + j] >> d) & 1u) << j;
        }
        krow[d][w] = rk; vrow[d][w] = rv;
    }
    __syncthreads();

    for (int p = tid; p < 1024; p += 256) {
        int dd = p >> 5, e = p & 31;
        int s = 0;
        #pragma unroll
        for (int w = 0; w < 32; w++)
            s += __popc(krow[dd][w] & vrow[e][w]);
        kvm[dd][e] = (float)s;
    }
    __syncthreads();

    const int tb = bid >> 3, h = bid & 7;
    const int nl = tid & 31;
    for (int e = tid >> 5; e < 32; e += 8) {
        float* out = g_xa + (size_t)tb * CN_ + (size_t)(h * 32 + e) * N_;
        for (int j = 0; j < 32; j++) {
            int n = nl + j * 32;
            unsigned qm = qb[n];
            float s = 0.f;
            if (qm) {
                #pragma unroll
                for (int dd = 0; dd < 32; dd++)
                    if (qm & (1u << dd)) s += kvm[dd][e];
            }
            out[n] = 0.125f * s;
        }
    }
}

// ---------------------------------------------------------------------------
// Transpose p_w (256x256) so sparse gathers over c are coalesced in o.
// ---------------------------------------------------------------------------
__global__ __launch_bounds__(256)
void wt_kernel(const float* __restrict__ pw)
{
    int idx = blockIdx.x * 256 + threadIdx.x;  // < 65536
    int o = idx & 255, c = idx >> 8;
    g_wt[c * 256 + o] = pw[o * 256 + c];
}

// ---------------------------------------------------------------------------
// Fused sparse p-GEMM + bias + BN + LIF(1.0) -> out.
// xs (bitpacked in g_bits[3]) is ~all-zero: per (n,t) column, if the 256-bit
// channel mask is empty, y[o] = (bias)*sc+sh (constant); else gather W^T rows
// over set bits in ascending c. Block: b = blockIdx.y, 64-wide n chunk.
// Warp layout: 8 warps = 8 o-rows, 32 lanes = 32 n -> coalesced stores.
// ---------------------------------------------------------------------------
__global__ __launch_bounds__(256)
void sparse_p_out_kernel(const float* __restrict__ pb,
                         const float* __restrict__ pg,
                         const float* __restrict__ pbt,
                         const float* __restrict__ pm,
                         const float* __restrict__ pv,
                         float* __restrict__ out)
{
    __shared__ unsigned mw[4][8][64];
    __shared__ unsigned fl[4][64];
    __shared__ float s_sc[256], s_sh[256], s_bi[256];

    const int n0 = blockIdx.x * 64;
    const int b  = blockIdx.y;
    const int tid = threadIdx.x;

    {
        float sc = pg[tid] * rsqrtf(pv[tid] + 1e-5f);
        s_sc[tid] = sc;
        s_sh[tid] = pbt[tid] - pm[tid] * sc;
        s_bi[tid] = pb[tid];
    }
    for (int i = tid; i < 2048; i += 256) {
        int nn = i & 63, w = (i >> 6) & 7, t = i >> 9;
        mw[t][w][nn] = g_bits[3][t * (B_ * 8 * N_) + (b * 8 + w) * N_ + n0 + nn];
    }
    __syncthreads();
    {
        int t = tid >> 6, nn = tid & 63;
        unsigned f = 0;
        #pragma unroll
        for (int w = 0; w < 8; w++) f |= mw[t][w][nn];
        fl[t][nn] = f;
    }
    __syncthreads();

    const int wi = tid >> 5, lane = tid & 31;
    for (int og = 0; og < 32; og++) {
        int o = og * 8 + wi;
        float sc = s_sc[o], sh = s_sh[o], bi = s_bi[o];
        float v0 = bi * sc + sh;
        #pragma unroll
        for (int nn2 = 0; nn2 < 2; nn2++) {
            int nn = nn2 * 32 + lane;
            float mem = 0.f;
            #pragma unroll
            for (int t = 0; t < 4; t++) {
                float y = v0;
                if (fl[t][nn]) {
                    float acc = 0.f;
                    #pragma unroll 1
                    for (int w = 0; w < 8; w++) {
                        unsigned m = mw[t][w][nn];
                        while (m) {
                            int d = __ffs(m) - 1;
                            m &= m - 1;
                            acc += g_wt[(w * 32 + d) * 256 + o];
                        }
                    }
                    y = (acc + bi) * sc + sh;
                }
                mem += (y - mem) * 0.5f;
                float s = (mem >= 1.0f) ? 1.0f : 0.0f;
                out[(size_t)t * BCN + (size_t)b * CN_ + (size_t)o * N_ + n0 + nn] = s;
                mem *= (1.0f - s);
            }
        }
    }
}

// ---------------------------------------------------------------------------
extern "C" void kernel_launch(void* const* d_in, const int* in_sizes, int n_in,
                              void* d_out, int out_size)
{
    const float* x  = (const float*)d_in[0];
    const float* qw = (const float*)d_in[2];
    const float* qg = (const float*)d_in[3];
    const float* qb = (const float*)d_in[4];
    const float* qm = (const float*)d_in[5];
    const float* qv = (const float*)d_in[6];
    const float* kw = (const float*)d_in[7];
    const float* kg = (const float*)d_in[8];
    const float* kb = (const float*)d_in[9];
    const float* km = (const float*)d_in[10];
    const float* kv = (const float*)d_in[11];
    const float* vw = (const float*)d_in[12];
    const float* vg = (const float*)d_in[13];
    const float* vb = (const float*)d_in[14];
    const float* vm = (const float*)d_in[15];
    const float* vv = (const float*)d_in[16];
    const float* pw = (const float*)d_in[17];
    const float* pb = (const float*)d_in[18];
    const float* pg = (const float*)d_in[19];
    const float* pbt = (const float*)d_in[20];
    const float* pm = (const float*)d_in[21];
    const float* pv = (const float*)d_in[22];

    float* out  = (float*)d_out;
    float* vout = out + TBCN;

    // one-shot W^T for the sparse p path (independent, launch first)
    wt_kernel<<<C_ * C_ / 256, 256>>>(pw);

    dim3 ggrid(N_ / 128, C_ / 128, T_ * B_);
    gemm_bn_kernel<<<ggrid, 256>>>(x, 0, qw, qg, qb, qm, qv);
    gemm_bn_kernel<<<ggrid, 256>>>(x, 1, kw, kg, kb, km, kv);
    gemm_bn_kernel<<<ggrid, 256>>>(x, 2, vw, vg, vb, vm, vv);

    // LIF(1.0) + bitpack for q,k,v
    lif_pack_kernel<<<dim3((B_ * 8 * N_) / 256, 3), 256>>>(0, 1.0f);

    // v output
    if (out_size >= 2 * TBCN)
        v_writer_kernel<<<TBCN / 256, 256>>>(vout);

    // kv + attn -> g_xa
    kv_attn_kernel<<<T_ * B_ * 8, 256>>>();

    // LIF(0.5) + bitpack xs -> g_bits[3]
    lif_pack_kernel<<<dim3((B_ * 8 * N_) / 256, 1), 256>>>(3, 0.5f);

    // fused sparse p-GEMM + BN + LIF(1.0) -> out
    sparse_p_out_kernel<<<dim3(N_ / 64, B_), 256>>>(pb, pg, pbt, pm, pv, out);
}

// round 6
// speedup vs baseline: 1.9024x; 1.3825x over previous
#include <cuda_runtime.h>
#include <cuda_bf16.h>
#include <mma.h>
#include <cstdint>

using namespace nvcuda;

#define T_ 4
#define B_ 16
#define C_ 256
#define N_ 1024
#define CN_ (C_*N_)          // 262144
#define BCN (B_*C_*N_)       // 4194304
#define TBCN (T_*BCN)        // 16777216
#define NBITS (T_*B_*8*N_)   // 524288 words per branch

// Scratch (device globals: allocation-free)
__device__ float    g_y[3][TBCN];     // post-BN pre-LIF activations for q,k,v
__device__ unsigned g_bits[4][NBITS]; // spike bitpacks: q,k,v, xs
__device__ float    g_xa[TBCN];       // attention output (pre-LIF2)
__device__ float    g_wt[C_*C_];      // p_w transposed
__device__ __align__(16) __nv_bfloat16 g_wsplit[3][3][C_*C_]; // 3-way bf16 split of q/k/v W

// ===========================================================================
// One-shot: 3-way bf16 split of q/k/v weights
// ===========================================================================
__global__ __launch_bounds__(256)
void wsplit_kernel(const float* __restrict__ qw, const float* __restrict__ kw,
                   const float* __restrict__ vw)
{
    int idx = blockIdx.x * 256 + threadIdx.x;         // < 3*65536
    int proj = idx >> 16, e = idx & 65535;
    const float* W = proj == 0 ? qw : (proj == 1 ? kw : vw);
    float x = W[e];
    __nv_bfloat16 b1 = __float2bfloat16_rn(x);
    float r = x - __bfloat162float(b1);
    __nv_bfloat16 b2 = __float2bfloat16_rn(r);
    float r2 = r - __bfloat162float(b2);
    __nv_bfloat16 b3 = __float2bfloat16_rn(r2);
    g_wsplit[proj][0][e] = b1;
    g_wsplit[proj][1][e] = b2;
    g_wsplit[proj][2][e] = b3;
}

// ===========================================================================
// WMMA (legacy HMMA) projection GEMM + BN, fp32-accurate via 6-term bf16 split
// Block: 128(o) x 128(n) tile of one tb; K=256 in 4 slabs of 64.
// Warp (8 total): 32(o) x 64(n) = 2x4 wmma 16x16 tiles.
// ===========================================================================
#define LDW 72                                  // Ws row ld (bf16 elements)
#define LDX 136                                 // Xs row ld
#define SW_OFF 0
#define SW_BYTES (3*128*LDW*2)                  // 55296
#define SX_OFF SW_BYTES
#define SX_BYTES (3*64*LDX*2)                   // 52224
#define SMEM_GT (SX_OFF + SX_BYTES)             // 107520 (stage f32 128x132 overlaps at 0)

__global__ __launch_bounds__(256, 2)
void gemm_wmma_kernel(const float* __restrict__ X, int proj,
                      const float* __restrict__ gamma, const float* __restrict__ beta,
                      const float* __restrict__ mean,  const float* __restrict__ var)
{
    extern __shared__ __align__(16) char smem[];
    __nv_bfloat16* Ws = (__nv_bfloat16*)(smem + SW_OFF);  // [3][128][LDW]
    __nv_bfloat16* Xs = (__nv_bfloat16*)(smem + SX_OFF);  // [3][64][LDX]
    float* stage = (float*)smem;                          // [128][132] (reuse)

    const int tid = threadIdx.x, wid = tid >> 5;
    const int n0 = blockIdx.x * 128;
    const int m0 = blockIdx.y * 128;
    const int tb = blockIdx.z;
    const float* Xb = X + (size_t)tb * CN_;
    float* Yb = g_y[proj] + (size_t)tb * CN_;

    const int wo = wid & 3;    // o-group (32 rows)
    const int wn = wid >> 2;   // n-group (64 cols)

    wmma::fragment<wmma::accumulator, 16, 16, 16, float> acc[2][4];
    #pragma unroll
    for (int i = 0; i < 2; i++)
        #pragma unroll
        for (int j = 0; j < 4; j++) wmma::fill_fragment(acc[i][j], 0.0f);

    for (int s = 0; s < 4; s++) {
        __syncthreads();   // previous slab's mma reads done

        // --- W split terms: [3][128 o][64 c] bf16 (pre-split in global) ---
        #pragma unroll
        for (int p = 0; p < 12; p++) {
            int ch = p * 256 + tid;            // < 3072 uint4s
            int t = ch >> 10, r = (ch >> 3) & 127, v = ch & 7;
            uint4 w4 = *(const uint4*)(g_wsplit[proj][t] + (m0 + r) * 256 + s * 64 + v * 8);
            *(uint4*)(Ws + t * 128 * LDW + r * LDW + v * 8) = w4;
        }
        // --- X slab: load f32 [64 c][128 n], split to 3 bf16 tiles ---
        #pragma unroll
        for (int p = 0; p < 8; p++) {
            int ch = p * 256 + tid;            // < 2048 float4s
            int r = ch >> 5, v = ch & 31;
            float4 xv = *(const float4*)(Xb + (size_t)(s * 64 + r) * N_ + n0 + v * 4);
            float xin[4] = {xv.x, xv.y, xv.z, xv.w};
            __nv_bfloat16 t1[4], t2[4], t3[4];
            #pragma unroll
            for (int j = 0; j < 4; j++) {
                t1[j] = __float2bfloat16_rn(xin[j]);
                float r1 = xin[j] - __bfloat162float(t1[j]);
                t2[j] = __float2bfloat16_rn(r1);
                t3[j] = __float2bfloat16_rn(r1 - __bfloat162float(t2[j]));
            }
            *(uint2*)(Xs + 0 * 64 * LDX + r * LDX + v * 4) = *(uint2*)t1;
            *(uint2*)(Xs + 1 * 64 * LDX + r * LDX + v * 4) = *(uint2*)t2;
            *(uint2*)(Xs + 2 * 64 * LDX + r * LDX + v * 4) = *(uint2*)t3;
        }
        __syncthreads();

        // --- mma: 4 k-steps x (6 A-frags, 12 B-frags, 48 mma) per warp ---
        #pragma unroll
        for (int ks = 0; ks < 4; ks++) {
            wmma::fragment<wmma::matrix_a, 16, 16, 16, __nv_bfloat16, wmma::row_major> af[2][3];
            #pragma unroll
            for (int io = 0; io < 2; io++)
                #pragma unroll
                for (int t = 0; t < 3; t++)
                    wmma::load_matrix_sync(af[io][t],
                        Ws + t * 128 * LDW + (wo * 32 + io * 16) * LDW + ks * 16, LDW);
            #pragma unroll
            for (int jn = 0; jn < 4; jn++) {
                wmma::fragment<wmma::matrix_b, 16, 16, 16, __nv_bfloat16, wmma::row_major> bf[3];
                #pragma unroll
                for (int t = 0; t < 3; t++)
                    wmma::load_matrix_sync(bf[t],
                        Xs + t * 64 * LDX + ks * 16 * LDX + wn * 64 + jn * 16, LDX);
                #pragma unroll
                for (int io = 0; io < 2; io++) {
                    wmma::mma_sync(acc[io][jn], af[io][0], bf[0], acc[io][jn]);
                    wmma::mma_sync(acc[io][jn], af[io][1], bf[0], acc[io][jn]);
                    wmma::mma_sync(acc[io][jn], af[io][0], bf[1], acc[io][jn]);
                    wmma::mma_sync(acc[io][jn], af[io][2], bf[0], acc[io][jn]);
                    wmma::mma_sync(acc[io][jn], af[io][0], bf[2], acc[io][jn]);
                    wmma::mma_sync(acc[io][jn], af[io][1], bf[1], acc[io][jn]);
                }
            }
        }
    }
    __syncthreads();

    // --- epilogue: frags -> smem stage, then BN + coalesced writes ---
    #pragma unroll
    for (int io = 0; io < 2; io++)
        #pragma unroll
        for (int jn = 0; jn < 4; jn++)
            wmma::store_matrix_sync(stage + (wo * 32 + io * 16) * 132 + wn * 64 + jn * 16,
                                    acc[io][jn], 132, wmma::mem_row_major);
    __syncthreads();

    #pragma unroll
    for (int p = 0; p < 16; p++) {
        int idx = p * 256 + tid;            // < 4096 float4s
        int row = idx >> 5, c4 = (idx & 31) * 4;
        int o = m0 + row;
        float sc = gamma[o] * rsqrtf(var[o] + 1e-5f);
        float sh = beta[o] - mean[o] * sc;
        const float* sp = stage + row * 132 + c4;
        float4 yv = make_float4(sp[0] * sc + sh, sp[1] * sc + sh,
                                sp[2] * sc + sh, sp[3] * sc + sh);
        *(float4*)(Yb + (size_t)o * N_ + n0 + c4) = yv;
    }
}

// ===========================================================================
// LIF over T + bitpack (unchanged)
// ===========================================================================
__global__ __launch_bounds__(256)
void lif_pack_kernel(int proj_base, float vth)
{
    const int proj = proj_base + blockIdx.y;
    const int idx = blockIdx.x * 256 + threadIdx.x;
    const int n = idx & (N_ - 1);
    const int h = (idx >> 10) & 7;
    const int b = idx >> 13;
    const float* Y = (proj < 3) ? g_y[proj] : g_xa;

    unsigned bits[4] = {0u, 0u, 0u, 0u};
    for (int d = 0; d < 32; d++) {
        const float* p = Y + (size_t)b * CN_ + (size_t)(h * 32 + d) * N_ + n;
        float mem = 0.f;
        #pragma unroll
        for (int t = 0; t < 4; t++) {
            float y = p[(size_t)t * BCN];
            mem += (y - mem) * 0.5f;
            if (mem >= vth) { bits[t] |= (1u << d); mem = 0.f; }
        }
    }
    const int ob = (b * 8 + h) * N_ + n;
    #pragma unroll
    for (int t = 0; t < 4; t++)
        g_bits[proj][t * (B_ * 8 * N_) + ob] = bits[t];
}

__global__ __launch_bounds__(256)
void v_writer_kernel(float* __restrict__ vout)
{
    const int idx = blockIdx.x * 256 + threadIdx.x;
    unsigned w = g_bits[2][idx >> 5];
    vout[idx] = (float)((w >> (idx & 31)) & 1u);
}

__global__ __launch_bounds__(256)
void kv_attn_kernel()
{
    __shared__ unsigned qb[1024], kb[1024], vb[1024];
    __shared__ unsigned krow[32][33], vrow[32][33];
    __shared__ float kvm[32][33];

    const int bid = blockIdx.x;
    const int tid = threadIdx.x;
    const unsigned base = (unsigned)bid * 1024u;

    for (int i = tid; i < 1024; i += 256) {
        qb[i] = g_bits[0][base + i];
        kb[i] = g_bits[1][base + i];
        vb[i] = g_bits[2][base + i];
    }
    __syncthreads();

    const int d = tid & 31;
    for (int w = tid >> 5; w < 32; w += 8) {
        unsigned rk = 0u, rv = 0u;
        #pragma unroll
        for (int j = 0; j < 32; j++) {
            rk |= ((kb[w * 32 + j] >> d) & 1u) << j;
            rv |= ((vb[w * 32 + j] >> d) & 1u) << j;
        }
        krow[d][w] = rk; vrow[d][w] = rv;
    }
    __syncthreads();

    for (int p = tid; p < 1024; p += 256) {
        int dd = p >> 5, e = p & 31;
        int s = 0;
        #pragma unroll
        for (int w = 0; w < 32; w++)
            s += __popc(krow[dd][w] & vrow[e][w]);
        kvm[dd][e] = (float)s;
    }
    __syncthreads();

    const int tb = bid >> 3, h = bid & 7;
    const int nl = tid & 31;
    for (int e = tid >> 5; e < 32; e += 8) {
        float* out = g_xa + (size_t)tb * CN_ + (size_t)(h * 32 + e) * N_;
        for (int j = 0; j < 32; j++) {
            int n = nl + j * 32;
            unsigned qm = qb[n];
            float s = 0.f;
            if (qm) {
                #pragma unroll
                for (int dd = 0; dd < 32; dd++)
                    if (qm & (1u << dd)) s += kvm[dd][e];
            }
            out[n] = 0.125f * s;
        }
    }
}

__global__ __launch_bounds__(256)
void wt_kernel(const float* __restrict__ pw)
{
    int idx = blockIdx.x * 256 + threadIdx.x;
    int o = idx & 255, c = idx >> 8;
    g_wt[c * 256 + o] = pw[o * 256 + c];
}

__global__ __launch_bounds__(256)
void sparse_p_out_kernel(const float* __restrict__ pb,
                         const float* __restrict__ pg,
                         const float* __restrict__ pbt,
                         const float* __restrict__ pm,
                         const float* __restrict__ pv,
                         float* __restrict__ out)
{
    __shared__ unsigned mw[4][8][64];
    __shared__ unsigned fl[4][64];
    __shared__ float s_sc[256], s_sh[256], s_bi[256];

    const int n0 = blockIdx.x * 64;
    const int b  = blockIdx.y;
    const int tid = threadIdx.x;

    {
        float sc = pg[tid] * rsqrtf(pv[tid] + 1e-5f);
        s_sc[tid] = sc;
        s_sh[tid] = pbt[tid] - pm[tid] * sc;
        s_bi[tid] = pb[tid];
    }
    for (int i = tid; i < 2048; i += 256) {
        int nn = i & 63, w = (i >> 6) & 7, t = i >> 9;
        mw[t][w][nn] = g_bits[3][t * (B_ * 8 * N_) + (b * 8 + w) * N_ + n0 + nn];
    }
    __syncthreads();
    {
        int t = tid >> 6, nn = tid & 63;
        unsigned f = 0;
        #pragma unroll
        for (int w = 0; w < 8; w++) f |= mw[t][w][nn];
        fl[t][nn] = f;
    }
    __syncthreads();

    const int wi = tid >> 5, lane = tid & 31;
    for (int og = 0; og < 32; og++) {
        int o = og * 8 + wi;
        float sc = s_sc[o], sh = s_sh[o], bi = s_bi[o];
        float v0 = bi * sc + sh;
        #pragma unroll
        for (int nn2 = 0; nn2 < 2; nn2++) {
            int nn = nn2 * 32 + lane;
            float mem = 0.f;
            #pragma unroll
            for (int t = 0; t < 4; t++) {
                float y = v0;
                if (fl[t][nn]) {
                    float acc = 0.f;
                    #pragma unroll 1
                    for (int w = 0; w < 8; w++) {
                        unsigned m = mw[t][w][nn];
                        while (m) {
                            int d = __ffs(m) - 1;
                            m &= m - 1;
                            acc += g_wt[(w * 32 + d) * 256 + o];
                        }
                    }
                    y = (acc + bi) * sc + sh;
                }
                mem += (y - mem) * 0.5f;
                float s = (mem >= 1.0f) ? 1.0f : 0.0f;
                out[(size_t)t * BCN + (size_t)b * CN_ + (size_t)o * N_ + n0 + nn] = s;
                mem *= (1.0f - s);
            }
        }
    }
}

// ===========================================================================
extern "C" void kernel_launch(void* const* d_in, const int* in_sizes, int n_in,
                              void* d_out, int out_size)
{
    const float* x  = (const float*)d_in[0];
    const float* qw = (const float*)d_in[2];
    const float* qg = (const float*)d_in[3];
    const float* qb = (const float*)d_in[4];
    const float* qm = (const float*)d_in[5];
    const float* qv = (const float*)d_in[6];
    const float* kw = (const float*)d_in[7];
    const float* kg = (const float*)d_in[8];
    const float* kb = (const float*)d_in[9];
    const float* km = (const float*)d_in[10];
    const float* kv = (const float*)d_in[11];
    const float* vw = (const float*)d_in[12];
    const float* vg = (const float*)d_in[13];
    const float* vb = (const float*)d_in[14];
    const float* vm = (const float*)d_in[15];
    const float* vv = (const float*)d_in[16];
    const float* pw = (const float*)d_in[17];
    const float* pb = (const float*)d_in[18];
    const float* pg = (const float*)d_in[19];
    const float* pbt = (const float*)d_in[20];
    const float* pm = (const float*)d_in[21];
    const float* pv = (const float*)d_in[22];

    float* out  = (float*)d_out;
    float* vout = out + TBCN;

    static int smem_set = 0;
    if (!smem_set) {
        cudaFuncSetAttribute(gemm_wmma_kernel,
                             cudaFuncAttributeMaxDynamicSharedMemorySize, SMEM_GT);
        smem_set = 1;
    }

    // one-shot weight preps
    wsplit_kernel<<<3 * C_ * C_ / 256, 256>>>(qw, kw, vw);
    wt_kernel<<<C_ * C_ / 256, 256>>>(pw);

    // q,k,v projections via wmma (bf16 6-term split, fp32-accurate)
    dim3 tgrid(N_ / 128, C_ / 128, T_ * B_);
    gemm_wmma_kernel<<<tgrid, 256, SMEM_GT>>>(x, 0, qg, qb, qm, qv);
    gemm_wmma_kernel<<<tgrid, 256, SMEM_GT>>>(x, 1, kg, kb, km, kv);
    gemm_wmma_kernel<<<tgrid, 256, SMEM_GT>>>(x, 2, vg, vb, vm, vv);

    // LIF(1.0) + bitpack for q,k,v
    lif_pack_kernel<<<dim3((B_ * 8 * N_) / 256, 3), 256>>>(0, 1.0f);

    // v output
    if (out_size >= 2 * TBCN)
        v_writer_kernel<<<TBCN / 256, 256>>>(vout);

    // kv + attn -> g_xa
    kv_attn_kernel<<<T_ * B_ * 8, 256>>>();

    // LIF(0.5) + bitpack xs -> g_bits[3]
    lif_pack_kernel<<<dim3((B_ * 8 * N_) / 256, 1), 256>>>(3, 0.5f);

    // fused sparse p-GEMM + BN + LIF(1.0) -> out
    sparse_p_out_kernel<<<dim3(N_ / 64, B_), 256>>>(pb, pg, pbt, pm, pv, out);
}

// round 7
// speedup vs baseline: 1.9264x; 1.0126x over previous
#include <cuda_runtime.h>
#include <cuda_bf16.h>
#include <mma.h>
#include <cstdint>

using namespace nvcuda;

#define T_ 4
#define B_ 16
#define C_ 256
#define N_ 1024
#define CN_ (C_*N_)          // 262144
#define BCN (B_*C_*N_)       // 4194304
#define TBCN (T_*BCN)        // 16777216
#define NBITS (T_*B_*8*N_)   // 524288 words per branch

// Scratch (device globals: allocation-free)
__device__ float    g_y[3][TBCN];     // post-BN pre-LIF activations for q,k,v
__device__ unsigned g_bits[4][NBITS]; // spike bitpacks: q,k,v, xs
__device__ float    g_xa[TBCN];       // attention output (pre-LIF2)
__device__ float    g_wt[C_*C_];      // p_w transposed
__device__ __align__(16) __nv_bfloat16 g_wsplit[3][3][C_*C_]; // 3-way bf16 split of q/k/v W

__device__ __forceinline__ uint32_t smem_u32(const void* p) {
    return (uint32_t)__cvta_generic_to_shared(p);
}
__device__ __forceinline__ void cp_async16(uint32_t saddr, const void* g) {
    asm volatile("cp.async.ca.shared.global [%0], [%1], 16;" :: "r"(saddr), "l"(g));
}

// ===========================================================================
// One-shot: 3-way bf16 split of q/k/v weights
// ===========================================================================
__global__ __launch_bounds__(256)
void wsplit_kernel(const float* __restrict__ qw, const float* __restrict__ kw,
                   const float* __restrict__ vw)
{
    int idx = blockIdx.x * 256 + threadIdx.x;         // < 3*65536
    int proj = idx >> 16, e = idx & 65535;
    const float* W = proj == 0 ? qw : (proj == 1 ? kw : vw);
    float x = W[e];
    __nv_bfloat16 b1 = __float2bfloat16_rn(x);
    float r = x - __bfloat162float(b1);
    __nv_bfloat16 b2 = __float2bfloat16_rn(r);
    float r2 = r - __bfloat162float(b2);
    __nv_bfloat16 b3 = __float2bfloat16_rn(r2);
    g_wsplit[proj][0][e] = b1;
    g_wsplit[proj][1][e] = b2;
    g_wsplit[proj][2][e] = b3;
}

// ===========================================================================
// Pipelined WMMA projection GEMM + BN (fp32-accurate, 6-term bf16 split).
// One launch for all of q/k/v: blockIdx.z = tb*3 + proj.
// K in 8 slabs of 32; W double-buffered via cp.async; X reg-prefetched.
// Block: 128(o) x 128(n); warp: 32(o) x 64(n).
// ===========================================================================
#define KS 32
#define NSLAB 8
#define LDW2 40                                    // 32 bf16 + 8 pad
#define LDX2 136                                   // 128 bf16 + 8 pad
#define WBUF_BYTES (3*128*LDW2*2)                  // 30720
#define XS_OFF (2*WBUF_BYTES)                      // 61440
#define XS_BYTES (3*KS*LDX2*2)                     // 26112
#define SMEM_GT (XS_OFF + XS_BYTES)                // 87552

__global__ __launch_bounds__(256, 2)
void gemm_wmma_kernel(const float* __restrict__ X,
                      const float* __restrict__ qg, const float* __restrict__ qb,
                      const float* __restrict__ qm, const float* __restrict__ qv,
                      const float* __restrict__ kg, const float* __restrict__ kb,
                      const float* __restrict__ km, const float* __restrict__ kv,
                      const float* __restrict__ vg, const float* __restrict__ vb,
                      const float* __restrict__ vm, const float* __restrict__ vv)
{
    extern __shared__ __align__(16) char smem[];
    __nv_bfloat16* Xs = (__nv_bfloat16*)(smem + XS_OFF);  // [3][KS][LDX2]
    float* stage = (float*)smem;                          // [128][132] (reuse)

    const int tid = threadIdx.x, wid = tid >> 5;
    const int n0 = blockIdx.x * 128;
    const int m0 = blockIdx.y * 128;
    const int proj = blockIdx.z % 3;
    const int tb = blockIdx.z / 3;
    const float* Xb = X + (size_t)tb * CN_;
    float* Yb = g_y[proj] + (size_t)tb * CN_;

    const float* gamma = proj == 0 ? qg : (proj == 1 ? kg : vg);
    const float* beta  = proj == 0 ? qb : (proj == 1 ? kb : vb);
    const float* mean  = proj == 0 ? qm : (proj == 1 ? km : vm);
    const float* var   = proj == 0 ? qv : (proj == 1 ? kv : vv);
    const __nv_bfloat16* Wg = g_wsplit[proj][0];  // terms contiguous: [t][256*256]

    const int wo = wid & 3;    // o-group (32 rows)
    const int wn = wid >> 2;   // n-group (64 cols)

    const uint32_t ws_base = smem_u32(smem);

    // per-thread W cp.async chunk coords (6 chunks of 16B per slab)
    // ch = p*256+tid < 1536 : t = ch>>9, r = (ch>>2)&127, v = ch&3
    // per-thread X ldg coords (4 float4 per slab)
    // ch = p*256+tid < 1024 : r = ch>>5, v = ch&31
    const int xr_r = tid >> 5;       // base row for p=0 (rows step by 8 per p)
    const int xr_v = tid & 31;

    wmma::fragment<wmma::accumulator, 16, 16, 16, float> acc[2][4];
    #pragma unroll
    for (int i = 0; i < 2; i++)
        #pragma unroll
        for (int j = 0; j < 4; j++) wmma::fill_fragment(acc[i][j], 0.0f);

    // --- prologue: W slab 0 -> buf 0, X slab 0 -> regs ---
    #pragma unroll
    for (int p = 0; p < 6; p++) {
        int ch = p * 256 + tid;
        int t = ch >> 9, r = (ch >> 2) & 127, v = ch & 3;
        cp_async16(ws_base + (uint32_t)((t * 128 + r) * LDW2 * 2 + v * 16),
                   g_wsplit[proj][t] + (m0 + r) * 256 + v * 8);
    }
    asm volatile("cp.async.commit_group;");
    float4 xr[4];
    #pragma unroll
    for (int p = 0; p < 4; p++)
        xr[p] = *(const float4*)(Xb + (size_t)(xr_r + p * 8) * N_ + n0 + xr_v * 4);

    for (int s = 0; s < NSLAB; s++) {
        const int buf = s & 1;

        // --- convert current X regs -> Xs (3 split terms) ---
        #pragma unroll
        for (int p = 0; p < 4; p++) {
            int r = xr_r + p * 8;
            float xin[4] = {xr[p].x, xr[p].y, xr[p].z, xr[p].w};
            __nv_bfloat16 t1[4], t2[4], t3[4];
            #pragma unroll
            for (int j = 0; j < 4; j++) {
                t1[j] = __float2bfloat16_rn(xin[j]);
                float r1 = xin[j] - __bfloat162float(t1[j]);
                t2[j] = __float2bfloat16_rn(r1);
                t3[j] = __float2bfloat16_rn(r1 - __bfloat162float(t2[j]));
            }
            *(uint2*)(Xs + 0 * KS * LDX2 + r * LDX2 + xr_v * 4) = *(uint2*)t1;
            *(uint2*)(Xs + 1 * KS * LDX2 + r * LDX2 + xr_v * 4) = *(uint2*)t2;
            *(uint2*)(Xs + 2 * KS * LDX2 + r * LDX2 + xr_v * 4) = *(uint2*)t3;
        }

        if (s < NSLAB - 1) {
            // --- prefetch W slab s+1 into alternate buffer ---
            uint32_t wb = ws_base + (uint32_t)((buf ^ 1) * WBUF_BYTES);
            #pragma unroll
            for (int p = 0; p < 6; p++) {
                int ch = p * 256 + tid;
                int t = ch >> 9, r = (ch >> 2) & 127, v = ch & 3;
                cp_async16(wb + (uint32_t)((t * 128 + r) * LDW2 * 2 + v * 16),
                           g_wsplit[proj][t] + (m0 + r) * 256 + (s + 1) * KS + v * 8);
            }
            asm volatile("cp.async.commit_group;");
            // --- prefetch X slab s+1 into regs (consumed next iter) ---
            #pragma unroll
            for (int p = 0; p < 4; p++)
                xr[p] = *(const float4*)(Xb + (size_t)((s + 1) * KS + xr_r + p * 8) * N_ + n0 + xr_v * 4);
            asm volatile("cp.async.wait_group 1;");
        } else {
            asm volatile("cp.async.wait_group 0;");
        }
        __syncthreads();

        // --- mma over slab s (W from buf, X from Xs) ---
        const __nv_bfloat16* Wb = (const __nv_bfloat16*)(smem + buf * WBUF_BYTES);
        #pragma unroll
        for (int ks = 0; ks < 2; ks++) {
            wmma::fragment<wmma::matrix_a, 16, 16, 16, __nv_bfloat16, wmma::row_major> af[2][3];
            #pragma unroll
            for (int io = 0; io < 2; io++)
                #pragma unroll
                for (int t = 0; t < 3; t++)
                    wmma::load_matrix_sync(af[io][t],
                        Wb + t * 128 * LDW2 + (wo * 32 + io * 16) * LDW2 + ks * 16, LDW2);
            #pragma unroll
            for (int jn = 0; jn < 4; jn++) {
                wmma::fragment<wmma::matrix_b, 16, 16, 16, __nv_bfloat16, wmma::row_major> bf[3];
                #pragma unroll
                for (int t = 0; t < 3; t++)
                    wmma::load_matrix_sync(bf[t],
                        Xs + t * KS * LDX2 + ks * 16 * LDX2 + wn * 64 + jn * 16, LDX2);
                #pragma unroll
                for (int io = 0; io < 2; io++) {
                    wmma::mma_sync(acc[io][jn], af[io][0], bf[0], acc[io][jn]);
                    wmma::mma_sync(acc[io][jn], af[io][1], bf[0], acc[io][jn]);
                    wmma::mma_sync(acc[io][jn], af[io][0], bf[1], acc[io][jn]);
                    wmma::mma_sync(acc[io][jn], af[io][2], bf[0], acc[io][jn]);
                    wmma::mma_sync(acc[io][jn], af[io][0], bf[2], acc[io][jn]);
                    wmma::mma_sync(acc[io][jn], af[io][1], bf[1], acc[io][jn]);
                }
            }
        }
        __syncthreads();
    }

    // --- epilogue: frags -> smem stage, then BN + coalesced writes ---
    #pragma unroll
    for (int io = 0; io < 2; io++)
        #pragma unroll
        for (int jn = 0; jn < 4; jn++)
            wmma::store_matrix_sync(stage + (wo * 32 + io * 16) * 132 + wn * 64 + jn * 16,
                                    acc[io][jn], 132, wmma::mem_row_major);
    __syncthreads();

    #pragma unroll
    for (int p = 0; p < 16; p++) {
        int idx = p * 256 + tid;            // < 4096 float4s
        int row = idx >> 5, c4 = (idx & 31) * 4;
        int o = m0 + row;
        float sc = gamma[o] * rsqrtf(var[o] + 1e-5f);
        float sh = beta[o] - mean[o] * sc;
        const float* sp = stage + row * 132 + c4;
        float4 yv = make_float4(sp[0] * sc + sh, sp[1] * sc + sh,
                                sp[2] * sc + sh, sp[3] * sc + sh);
        *(float4*)(Yb + (size_t)o * N_ + n0 + c4) = yv;
    }
}

// ===========================================================================
// LIF over T + bitpack; proj==2 also writes the float v output directly.
// ===========================================================================
__global__ __launch_bounds__(256)
void lif_pack_kernel(int proj_base, float vth, float* __restrict__ vout)
{
    const int proj = proj_base + blockIdx.y;
    const int idx = blockIdx.x * 256 + threadIdx.x;
    const int n = idx & (N_ - 1);
    const int h = (idx >> 10) & 7;
    const int b = idx >> 13;
    const float* Y = (proj < 3) ? g_y[proj] : g_xa;

    unsigned bits[4] = {0u, 0u, 0u, 0u};
    for (int d = 0; d < 32; d++) {
        const float* p = Y + (size_t)b * CN_ + (size_t)(h * 32 + d) * N_ + n;
        float mem = 0.f;
        #pragma unroll
        for (int t = 0; t < 4; t++) {
            float y = p[(size_t)t * BCN];
            mem += (y - mem) * 0.5f;
            if (mem >= vth) { bits[t] |= (1u << d); mem = 0.f; }
        }
    }
    const int ob = (b * 8 + h) * N_ + n;
    #pragma unroll
    for (int t = 0; t < 4; t++)
        g_bits[proj][t * (B_ * 8 * N_) + ob] = bits[t];

    if (proj == 2 && vout) {
        #pragma unroll
        for (int t = 0; t < 4; t++) {
            unsigned w = bits[t];
            float4* vp = (float4*)(vout + ((size_t)(t * (B_ * 8) + b * 8 + h) * N_ + n) * 32);
            #pragma unroll
            for (int j = 0; j < 8; j++)
                vp[j] = make_float4((float)((w >> (4*j+0)) & 1u), (float)((w >> (4*j+1)) & 1u),
                                    (float)((w >> (4*j+2)) & 1u), (float)((w >> (4*j+3)) & 1u));
        }
    }
}

// ===========================================================================
// Per (t,b,h): kv[d][e] = popc over n of k_d & v_e; xa = 0.125 * q·kv.
// ===========================================================================
__global__ __launch_bounds__(256)
void kv_attn_kernel()
{
    __shared__ unsigned qb[1024], kb[1024], vb[1024];
    __shared__ unsigned krow[32][33], vrow[32][33];
    __shared__ float kvm[32][33];

    const int bid = blockIdx.x;
    const int tid = threadIdx.x;
    const unsigned base = (unsigned)bid * 1024u;

    for (int i = tid; i < 1024; i += 256) {
        qb[i] = g_bits[0][base + i];
        kb[i] = g_bits[1][base + i];
        vb[i] = g_bits[2][base + i];
    }
    __syncthreads();

    const int d = tid & 31;
    for (int w = tid >> 5; w < 32; w += 8) {
        unsigned rk = 0u, rv = 0u;
        #pragma unroll
        for (int j = 0; j < 32; j++) {
            rk |= ((kb[w * 32 + j] >> d) & 1u) << j;
            rv |= ((vb[w * 32 + j] >> d) & 1u) << j;
        }
        krow[d][w] = rk; vrow[d][w] = rv;
    }
    __syncthreads();

    for (int p = tid; p < 1024; p += 256) {
        int dd = p >> 5, e = p & 31;
        int s = 0;
        #pragma unroll
        for (int w = 0; w < 32; w++)
            s += __popc(krow[dd][w] & vrow[e][w]);
        kvm[dd][e] = (float)s;
    }
    __syncthreads();

    const int tb = bid >> 3, h = bid & 7;
    const int nl = tid & 31;
    for (int e = tid >> 5; e < 32; e += 8) {
        float* out = g_xa + (size_t)tb * CN_ + (size_t)(h * 32 + e) * N_;
        for (int j = 0; j < 32; j++) {
            int n = nl + j * 32;
            unsigned qm = qb[n];
            float s = 0.f;
            if (qm) {
                #pragma unroll
                for (int dd = 0; dd < 32; dd++)
                    if (qm & (1u << dd)) s += kvm[dd][e];
            }
            out[n] = 0.125f * s;
        }
    }
}

__global__ __launch_bounds__(256)
void wt_kernel(const float* __restrict__ pw)
{
    int idx = blockIdx.x * 256 + threadIdx.x;
    int o = idx & 255, c = idx >> 8;
    g_wt[c * 256 + o] = pw[o * 256 + c];
}

__global__ __launch_bounds__(256)
void sparse_p_out_kernel(const float* __restrict__ pb,
                         const float* __restrict__ pg,
                         const float* __restrict__ pbt,
                         const float* __restrict__ pm,
                         const float* __restrict__ pv,
                         float* __restrict__ out)
{
    __shared__ unsigned mw[4][8][64];
    __shared__ unsigned fl[4][64];
    __shared__ float s_sc[256], s_sh[256], s_bi[256];

    const int n0 = blockIdx.x * 64;
    const int b  = blockIdx.y;
    const int tid = threadIdx.x;

    {
        float sc = pg[tid] * rsqrtf(pv[tid] + 1e-5f);
        s_sc[tid] = sc;
        s_sh[tid] = pbt[tid] - pm[tid] * sc;
        s_bi[tid] = pb[tid];
    }
    for (int i = tid; i < 2048; i += 256) {
        int nn = i & 63, w = (i >> 6) & 7, t = i >> 9;
        mw[t][w][nn] = g_bits[3][t * (B_ * 8 * N_) + (b * 8 + w) * N_ + n0 + nn];
    }
    __syncthreads();
    {
        int t = tid >> 6, nn = tid & 63;
        unsigned f = 0;
        #pragma unroll
        for (int w = 0; w < 8; w++) f |= mw[t][w][nn];
        fl[t][nn] = f;
    }
    __syncthreads();

    const int wi = tid >> 5, lane = tid & 31;
    for (int og = 0; og < 32; og++) {
        int o = og * 8 + wi;
        float sc = s_sc[o], sh = s_sh[o], bi = s_bi[o];
        float v0 = bi * sc + sh;
        #pragma unroll
        for (int nn2 = 0; nn2 < 2; nn2++) {
            int nn = nn2 * 32 + lane;
            float mem = 0.f;
            #pragma unroll
            for (int t = 0; t < 4; t++) {
                float y = v0;
                if (fl[t][nn]) {
                    float acc = 0.f;
                    #pragma unroll 1
                    for (int w = 0; w < 8; w++) {
                        unsigned m = mw[t][w][nn];
                        while (m) {
                            int d = __ffs(m) - 1;
                            m &= m - 1;
                            acc += g_wt[(w * 32 + d) * 256 + o];
                        }
                    }
                    y = (acc + bi) * sc + sh;
                }
                mem += (y - mem) * 0.5f;
                float s = (mem >= 1.0f) ? 1.0f : 0.0f;
                out[(size_t)t * BCN + (size_t)b * CN_ + (size_t)o * N_ + n0 + nn] = s;
                mem *= (1.0f - s);
            }
        }
    }
}

// ===========================================================================
extern "C" void kernel_launch(void* const* d_in, const int* in_sizes, int n_in,
                              void* d_out, int out_size)
{
    const float* x  = (const float*)d_in[0];
    const float* qw = (const float*)d_in[2];
    const float* qg = (const float*)d_in[3];
    const float* qb = (const float*)d_in[4];
    const float* qm = (const float*)d_in[5];
    const float* qv = (const float*)d_in[6];
    const float* kw = (const float*)d_in[7];
    const float* kg = (const float*)d_in[8];
    const float* kb = (const float*)d_in[9];
    const float* km = (const float*)d_in[10];
    const float* kv = (const float*)d_in[11];
    const float* vw = (const float*)d_in[12];
    const float* vg = (const float*)d_in[13];
    const float* vb = (const float*)d_in[14];
    const float* vm = (const float*)d_in[15];
    const float* vv = (const float*)d_in[16];
    const float* pw = (const float*)d_in[17];
    const float* pb = (const float*)d_in[18];
    const float* pg = (const float*)d_in[19];
    const float* pbt = (const float*)d_in[20];
    const float* pm = (const float*)d_in[21];
    const float* pv = (const float*)d_in[22];

    float* out  = (float*)d_out;
    float* vout = (out_size >= 2 * TBCN) ? out + TBCN : nullptr;

    static int smem_set = 0;
    if (!smem_set) {
        cudaFuncSetAttribute(gemm_wmma_kernel,
                             cudaFuncAttributeMaxDynamicSharedMemorySize, SMEM_GT);
        smem_set = 1;
    }

    // one-shot weight preps
    wsplit_kernel<<<3 * C_ * C_ / 256, 256>>>(qw, kw, vw);
    wt_kernel<<<C_ * C_ / 256, 256>>>(pw);

    // q,k,v projections fused into one pipelined wmma launch
    dim3 tgrid(N_ / 128, C_ / 128, T_ * B_ * 3);
    gemm_wmma_kernel<<<tgrid, 256, SMEM_GT>>>(x, qg, qb, qm, qv,
                                              kg, kb, km, kv, vg, vb, vm, vv);

    // LIF(1.0) + bitpack for q,k,v (+ fused v output write)
    lif_pack_kernel<<<dim3((B_ * 8 * N_) / 256, 3), 256>>>(0, 1.0f, vout);

    // kv + attn -> g_xa
    kv_attn_kernel<<<T_ * B_ * 8, 256>>>();

    // LIF(0.5) + bitpack xs -> g_bits[3]
    lif_pack_kernel<<<dim3((B_ * 8 * N_) / 256, 1), 256>>>(3, 0.5f, nullptr);

    // fused sparse p-GEMM + BN + LIF(1.0) -> out
    sparse_p_out_kernel<<<dim3(N_ / 64, B_), 256>>>(pb, pg, pbt, pm, pv, out);
}

// round 9
// speedup vs baseline: 2.1804x; 1.1318x over previous
#include <cuda_runtime.h>
#include <cuda_fp16.h>
#include <mma.h>
#include <cstdint>

using namespace nvcuda;

#define T_ 4
#define B_ 16
#define C_ 256
#define N_ 1024
#define CN_ (C_*N_)          // 262144
#define BCN (B_*C_*N_)       // 4194304
#define TBCN (T_*BCN)        // 16777216
#define NBITS (T_*B_*8*N_)   // 524288 words per branch

// Scratch (device globals: allocation-free)
__device__ float    g_y[3][TBCN];     // post-BN pre-LIF activations for q,k,v
__device__ unsigned g_bits[4][NBITS]; // spike bitpacks: q,k,v, xs
__device__ float    g_xa[TBCN];       // attention output (pre-LIF2)
__device__ float    g_wt[C_*C_];      // p_w transposed
__device__ __align__(16) __half g_wsplit[3][2][C_*C_]; // fp16 2-term split of q/k/v W

__device__ __forceinline__ uint32_t smem_u32(const void* p) {
    return (uint32_t)__cvta_generic_to_shared(p);
}
__device__ __forceinline__ void cp_async16(uint32_t saddr, const void* g) {
    asm volatile("cp.async.ca.shared.global [%0], [%1], 16;" :: "r"(saddr), "l"(g));
}

// ===========================================================================
// One-shot: 2-term fp16 split of q/k/v weights (x ~ h1 + h2 to ~2^-22)
// ===========================================================================
__global__ __launch_bounds__(256)
void wsplit_kernel(const float* __restrict__ qw, const float* __restrict__ kw,
                   const float* __restrict__ vw)
{
    int idx = blockIdx.x * 256 + threadIdx.x;         // < 3*65536
    int proj = idx >> 16, e = idx & 65535;
    const float* W = proj == 0 ? qw : (proj == 1 ? kw : vw);
    float x = W[e];
    __half h1 = __float2half_rn(x);
    __half h2 = __float2half_rn(x - __half2float(h1));
    g_wsplit[proj][0][e] = h1;
    g_wsplit[proj][1][e] = h2;
}

// ===========================================================================
// Pipelined WMMA projection GEMM + BN (fp32-accurate, 3-term fp16 split).
// One launch for q/k/v: blockIdx.z = tb*3 + proj.
// K in 8 slabs of 32; W double-buffered via cp.async; X reg-prefetched.
// Block: 128(o) x 128(n); warp: 32(o) x 64(n).
// ===========================================================================
#define KS 32
#define NSLAB 8
#define LDW2 40                                    // 32 fp16 + 8 pad
#define LDX2 136                                   // 128 fp16 + 8 pad
#define WBUF_BYTES (2*128*LDW2*2)                  // 20480
#define XS_OFF (2*WBUF_BYTES)                      // 40960
#define XS_BYTES (2*KS*LDX2*2)                     // 17408
#define SMEM_GT (128*132*4)                        // 67584 (stage dominates)

__global__ __launch_bounds__(256, 2)
void gemm_wmma_kernel(const float* __restrict__ X,
                      const float* __restrict__ qg, const float* __restrict__ qb,
                      const float* __restrict__ qm, const float* __restrict__ qv,
                      const float* __restrict__ kg, const float* __restrict__ kb,
                      const float* __restrict__ km, const float* __restrict__ kv,
                      const float* __restrict__ vg, const float* __restrict__ vb,
                      const float* __restrict__ vm, const float* __restrict__ vv)
{
    extern __shared__ __align__(16) char smem[];
    __half* Xs = (__half*)(smem + XS_OFF);     // [2][KS][LDX2]
    float* stage = (float*)smem;               // [128][132] (epilogue reuse)

    const int tid = threadIdx.x, wid = tid >> 5;
    const int n0 = blockIdx.x * 128;
    const int m0 = blockIdx.y * 128;
    const int proj = blockIdx.z % 3;
    const int tb = blockIdx.z / 3;
    const float* Xb = X + (size_t)tb * CN_;
    float* Yb = g_y[proj] + (size_t)tb * CN_;

    const float* gamma = proj == 0 ? qg : (proj == 1 ? kg : vg);
    const float* beta  = proj == 0 ? qb : (proj == 1 ? kb : vb);
    const float* mean  = proj == 0 ? qm : (proj == 1 ? km : vm);
    const float* var   = proj == 0 ? qv : (proj == 1 ? kv : vv);

    const int wo = wid & 3;    // o-group (32 rows)
    const int wn = wid >> 2;   // n-group (64 cols)

    const uint32_t ws_base = smem_u32(smem);
    const int xr_r = tid >> 5;       // X ldg row base (rows step by 8)
    const int xr_v = tid & 31;

    wmma::fragment<wmma::accumulator, 16, 16, 16, float> acc[2][4];
    #pragma unroll
    for (int i = 0; i < 2; i++)
        #pragma unroll
        for (int j = 0; j < 4; j++) wmma::fill_fragment(acc[i][j], 0.0f);

    // --- prologue: W slab 0 (2 terms, 1024 x 16B chunks) + X slab 0 regs ---
    #pragma unroll
    for (int p = 0; p < 4; p++) {
        int ch = p * 256 + tid;                  // < 1024
        int t = ch >> 9, r = (ch >> 2) & 127, v = ch & 3;
        cp_async16(ws_base + (uint32_t)((t * 128 + r) * LDW2 * 2 + v * 16),
                   g_wsplit[proj][t] + (m0 + r) * 256 + v * 8);
    }
    asm volatile("cp.async.commit_group;");
    float4 xr[4];
    #pragma unroll
    for (int p = 0; p < 4; p++)
        xr[p] = *(const float4*)(Xb + (size_t)(xr_r + p * 8) * N_ + n0 + xr_v * 4);

    for (int s = 0; s < NSLAB; s++) {
        const int buf = s & 1;

        // --- convert current X regs -> Xs (2 fp16 terms) ---
        #pragma unroll
        for (int p = 0; p < 4; p++) {
            int r = xr_r + p * 8;
            float xin[4] = {xr[p].x, xr[p].y, xr[p].z, xr[p].w};
            __half t1[4], t2[4];
            #pragma unroll
            for (int j = 0; j < 4; j++) {
                t1[j] = __float2half_rn(xin[j]);
                t2[j] = __float2half_rn(xin[j] - __half2float(t1[j]));
            }
            *(uint2*)(Xs + 0 * KS * LDX2 + r * LDX2 + xr_v * 4) = *(uint2*)t1;
            *(uint2*)(Xs + 1 * KS * LDX2 + r * LDX2 + xr_v * 4) = *(uint2*)t2;
        }

        if (s < NSLAB - 1) {
            uint32_t wb = ws_base + (uint32_t)((buf ^ 1) * WBUF_BYTES);
            #pragma unroll
            for (int p = 0; p < 4; p++) {
                int ch = p * 256 + tid;
                int t = ch >> 9, r = (ch >> 2) & 127, v = ch & 3;
                cp_async16(wb + (uint32_t)((t * 128 + r) * LDW2 * 2 + v * 16),
                           g_wsplit[proj][t] + (m0 + r) * 256 + (s + 1) * KS + v * 8);
            }
            asm volatile("cp.async.commit_group;");
            #pragma unroll
            for (int p = 0; p < 4; p++)
                xr[p] = *(const float4*)(Xb + (size_t)((s + 1) * KS + xr_r + p * 8) * N_ + n0 + xr_v * 4);
            asm volatile("cp.async.wait_group 1;");
        } else {
            asm volatile("cp.async.wait_group 0;");
        }
        __syncthreads();

        // --- mma over slab s: terms (W1,X1), (W2,X1), (W1,X2) ---
        const __half* Wb = (const __half*)(smem + buf * WBUF_BYTES);
        #pragma unroll
        for (int ks = 0; ks < 2; ks++) {
            wmma::fragment<wmma::matrix_a, 16, 16, 16, __half, wmma::row_major> af[2][2];
            #pragma unroll
            for (int io = 0; io < 2; io++)
                #pragma unroll
                for (int t = 0; t < 2; t++)
                    wmma::load_matrix_sync(af[io][t],
                        Wb + t * 128 * LDW2 + (wo * 32 + io * 16) * LDW2 + ks * 16, LDW2);
            #pragma unroll
            for (int jn = 0; jn < 4; jn++) {
                wmma::fragment<wmma::matrix_b, 16, 16, 16, __half, wmma::row_major> bf[2];
                #pragma unroll
                for (int t = 0; t < 2; t++)
                    wmma::load_matrix_sync(bf[t],
                        Xs + t * KS * LDX2 + ks * 16 * LDX2 + wn * 64 + jn * 16, LDX2);
                #pragma unroll
                for (int io = 0; io < 2; io++) {
                    wmma::mma_sync(acc[io][jn], af[io][0], bf[0], acc[io][jn]);
                    wmma::mma_sync(acc[io][jn], af[io][1], bf[0], acc[io][jn]);
                    wmma::mma_sync(acc[io][jn], af[io][0], bf[1], acc[io][jn]);
                }
            }
        }
        __syncthreads();
    }

    // --- epilogue: frags -> smem stage, then BN + coalesced writes ---
    #pragma unroll
    for (int io = 0; io < 2; io++)
        #pragma unroll
        for (int jn = 0; jn < 4; jn++)
            wmma::store_matrix_sync(stage + (wo * 32 + io * 16) * 132 + wn * 64 + jn * 16,
                                    acc[io][jn], 132, wmma::mem_row_major);
    __syncthreads();

    #pragma unroll
    for (int p = 0; p < 16; p++) {
        int idx = p * 256 + tid;            // < 4096 float4s
        int row = idx >> 5, c4 = (idx & 31) * 4;
        int o = m0 + row;
        float sc = gamma[o] * rsqrtf(var[o] + 1e-5f);
        float sh = beta[o] - mean[o] * sc;
        const float* sp = stage + row * 132 + c4;
        float4 yv = make_float4(sp[0] * sc + sh, sp[1] * sc + sh,
                                sp[2] * sc + sh, sp[3] * sc + sh);
        *(float4*)(Yb + (size_t)o * N_ + n0 + c4) = yv;
    }
}

// ===========================================================================
// LIF over T + bitpack, 4 consecutive n per thread (float4/uint4 vectorized);
// proj==2 also writes the float v output directly.
// ===========================================================================
__global__ __launch_bounds__(256)
void lif_pack_kernel(int proj_base, float vth, float* __restrict__ vout)
{
    const int proj = proj_base + blockIdx.y;
    const int idx = blockIdx.x * 256 + threadIdx.x;  // < B*8*N/4 = 32768
    const int n4 = idx & 255;                        // n block of 4
    const int h = (idx >> 8) & 7;
    const int b = idx >> 11;
    const float* Y = (proj < 3) ? g_y[proj] : g_xa;

    unsigned bits[4][4] = {};
    const float* base = Y + (size_t)b * CN_ + (size_t)(h * 32) * N_ + n4 * 4;
    for (int d = 0; d < 32; d++) {
        const float* p = base + (size_t)d * N_;
        float mem[4] = {0.f, 0.f, 0.f, 0.f};
        #pragma unroll
        for (int t = 0; t < 4; t++) {
            float4 y = *(const float4*)(p + (size_t)t * BCN);
            float ya[4] = {y.x, y.y, y.z, y.w};
            #pragma unroll
            for (int j = 0; j < 4; j++) {
                mem[j] += (ya[j] - mem[j]) * 0.5f;
                if (mem[j] >= vth) { bits[t][j] |= (1u << d); mem[j] = 0.f; }
            }
        }
    }
    const int ob = (b * 8 + h) * N_ + n4 * 4;
    #pragma unroll
    for (int t = 0; t < 4; t++)
        *(uint4*)&g_bits[proj][t * (B_ * 8 * N_) + ob] = *(uint4*)bits[t];

    if (proj == 2 && vout) {
        #pragma unroll
        for (int t = 0; t < 4; t++)
            #pragma unroll
            for (int j = 0; j < 4; j++) {
                unsigned w = bits[t][j];
                float4* vp = (float4*)(vout +
                    ((size_t)(t * (B_ * 8) + b * 8 + h) * N_ + n4 * 4 + j) * 32);
                #pragma unroll
                for (int q = 0; q < 8; q++)
                    vp[q] = make_float4((float)((w >> (4*q+0)) & 1u), (float)((w >> (4*q+1)) & 1u),
                                        (float)((w >> (4*q+2)) & 1u), (float)((w >> (4*q+3)) & 1u));
            }
    }
}

// ===========================================================================
// Per (t,b,h): kv[d][e] = popc over n of k_d & v_e; xa = 0.125 * q·kv.
// ===========================================================================
__global__ __launch_bounds__(256)
void kv_attn_kernel()
{
    __shared__ unsigned qb[1024], kb[1024], vb[1024];
    __shared__ unsigned krow[32][33], vrow[32][33];
    __shared__ float kvm[32][33];

    const int bid = blockIdx.x;
    const int tid = threadIdx.x;
    const unsigned base = (unsigned)bid * 1024u;

    for (int i = tid; i < 1024; i += 256) {
        qb[i] = g_bits[0][base + i];
        kb[i] = g_bits[1][base + i];
        vb[i] = g_bits[2][base + i];
    }
    __syncthreads();

    const int d = tid & 31;
    for (int w = tid >> 5; w < 32; w += 8) {
        unsigned rk = 0u, rv = 0u;
        #pragma unroll
        for (int j = 0; j < 32; j++) {
            rk |= ((kb[w * 32 + j] >> d) & 1u) << j;
            rv |= ((vb[w * 32 + j] >> d) & 1u) << j;
        }
        krow[d][w] = rk; vrow[d][w] = rv;
    }
    __syncthreads();

    for (int p = tid; p < 1024; p += 256) {
        int dd = p >> 5, e = p & 31;
        int s = 0;
        #pragma unroll
        for (int w = 0; w < 32; w++)
            s += __popc(krow[dd][w] & vrow[e][w]);
        kvm[dd][e] = (float)s;
    }
    __syncthreads();

    const int tb = bid >> 3, h = bid & 7;
    const int nl = tid & 31;
    for (int e = tid >> 5; e < 32; e += 8) {
        float* out = g_xa + (size_t)tb * CN_ + (size_t)(h * 32 + e) * N_;
        for (int j = 0; j < 32; j++) {
            int n = nl + j * 32;
            unsigned qm = qb[n];
            float s = 0.f;
            if (qm) {
                #pragma unroll
                for (int dd = 0; dd < 32; dd++)
                    if (qm & (1u << dd)) s += kvm[dd][e];
            }
            out[n] = 0.125f * s;
        }
    }
}

__global__ __launch_bounds__(256)
void wt_kernel(const float* __restrict__ pw)
{
    int idx = blockIdx.x * 256 + threadIdx.x;
    int o = idx & 255, c = idx >> 8;
    g_wt[c * 256 + o] = pw[o * 256 + c];
}

__global__ __launch_bounds__(256)
void sparse_p_out_kernel(const float* __restrict__ pb,
                         const float* __restrict__ pg,
                         const float* __restrict__ pbt,
                         const float* __restrict__ pm,
                         const float* __restrict__ pv,
                         float* __restrict__ out)
{
    __shared__ unsigned mw[4][8][64];
    __shared__ unsigned fl[4][64];
    __shared__ float s_sc[256], s_sh[256], s_bi[256];

    const int n0 = blockIdx.x * 64;
    const int b  = blockIdx.y;
    const int tid = threadIdx.x;

    {
        float sc = pg[tid] * rsqrtf(pv[tid] + 1e-5f);
        s_sc[tid] = sc;
        s_sh[tid] = pbt[tid] - pm[tid] * sc;
        s_bi[tid] = pb[tid];
    }
    for (int i = tid; i < 2048; i += 256) {
        int nn = i & 63, w = (i >> 6) & 7, t = i >> 9;
        mw[t][w][nn] = g_bits[3][t * (B_ * 8 * N_) + (b * 8 + w) * N_ + n0 + nn];
    }
    __syncthreads();
    {
        int t = tid >> 6, nn = tid & 63;
        unsigned f = 0;
        #pragma unroll
        for (int w = 0; w < 8; w++) f |= mw[t][w][nn];
        fl[t][nn] = f;
    }
    __syncthreads();

    const int wi = tid >> 5, lane = tid & 31;
    for (int og = 0; og < 32; og++) {
        int o = og * 8 + wi;
        float sc = s_sc[o], sh = s_sh[o], bi = s_bi[o];
        float v0 = bi * sc + sh;
        #pragma unroll
        for (int nn2 = 0; nn2 < 2; nn2++) {
            int nn = nn2 * 32 + lane;
            float mem = 0.f;
            #pragma unroll
            for (int t = 0; t < 4; t++) {
                float y = v0;
                if (fl[t][nn]) {
                    float acc = 0.f;
                    #pragma unroll 1
                    for (int w = 0; w < 8; w++) {
                        unsigned m = mw[t][w][nn];
                        while (m) {
                            int d = __ffs(m) - 1;
                            m &= m - 1;
                            acc += g_wt[(w * 32 + d) * 256 + o];
                        }
                    }
                    y = (acc + bi) * sc + sh;
                }
                mem += (y - mem) * 0.5f;
                float s = (mem >= 1.0f) ? 1.0f : 0.0f;
                out[(size_t)t * BCN + (size_t)b * CN_ + (size_t)o * N_ + n0 + nn] = s;
                mem *= (1.0f - s);
            }
        }
    }
}

// ===========================================================================
extern "C" void kernel_launch(void* const* d_in, const int* in_sizes, int n_in,
                              void* d_out, int out_size)
{
    const float* x  = (const float*)d_in[0];
    const float* qw = (const float*)d_in[2];
    const float* qg = (const float*)d_in[3];
    const float* qb = (const float*)d_in[4];
    const float* qm = (const float*)d_in[5];
    const float* qv = (const float*)d_in[6];
    const float* kw = (const float*)d_in[7];
    const float* kg = (const float*)d_in[8];
    const float* kb = (const float*)d_in[9];
    const float* km = (const float*)d_in[10];
    const float* kv = (const float*)d_in[11];
    const float* vw = (const float*)d_in[12];
    const float* vg = (const float*)d_in[13];
    const float* vb = (const float*)d_in[14];
    const float* vm = (const float*)d_in[15];
    const float* vv = (const float*)d_in[16];
    const float* pw = (const float*)d_in[17];
    const float* pb = (const float*)d_in[18];
    const float* pg = (const float*)d_in[19];
    const float* pbt = (const float*)d_in[20];
    const float* pm = (const float*)d_in[21];
    const float* pv = (const float*)d_in[22];

    float* out  = (float*)d_out;
    float* vout = (out_size >= 2 * TBCN) ? out + TBCN : nullptr;

    static int smem_set = 0;
    if (!smem_set) {
        cudaFuncSetAttribute(gemm_wmma_kernel,
                             cudaFuncAttributeMaxDynamicSharedMemorySize, SMEM_GT);
        smem_set = 1;
    }

    // one-shot weight preps
    wsplit_kernel<<<3 * C_ * C_ / 256, 256>>>(qw, kw, vw);
    wt_kernel<<<C_ * C_ / 256, 256>>>(pw);

    // q,k,v projections fused into one pipelined wmma launch (fp16 3-term)
    dim3 tgrid(N_ / 128, C_ / 128, T_ * B_ * 3);
    gemm_wmma_kernel<<<tgrid, 256, SMEM_GT>>>(x, qg, qb, qm, qv,
                                              kg, kb, km, kv, vg, vb, vm, vv);

    // LIF(1.0) + bitpack for q,k,v (+ fused v output write)
    lif_pack_kernel<<<dim3((B_ * 8 * N_) / 1024, 3), 256>>>(0, 1.0f, vout);

    // kv + attn -> g_xa
    kv_attn_kernel<<<T_ * B_ * 8, 256>>>();

    // LIF(0.5) + bitpack xs -> g_bits[3]
    lif_pack_kernel<<<dim3((B_ * 8 * N_) / 1024, 1), 256>>>(3, 0.5f, nullptr);

    // fused sparse p-GEMM + BN + LIF(1.0) -> out
    sparse_p_out_kernel<<<dim3(N_ / 64, B_), 256>>>(pb, pg, pbt, pm, pv, out);
}

// round 10
// speedup vs baseline: 3.2343x; 1.4834x over previous
#include <cuda_runtime.h>
#include <cuda_fp16.h>
#include <mma.h>
#include <cstdint>

using namespace nvcuda;

#define T_ 4
#define B_ 16
#define C_ 256
#define N_ 1024
#define CN_ (C_*N_)          // 262144
#define BCN (B_*C_*N_)       // 4194304
#define TBCN (T_*BCN)        // 16777216
#define NBITS (T_*B_*8*N_)   // 524288 words per branch

// Scratch (device globals: allocation-free)
__device__ float    g_y[3][TBCN];     // post-BN pre-LIF activations for q,k,v
__device__ unsigned g_bits[4][NBITS]; // spike bitpacks: q,k,v, xs
__device__ float    g_kvm[T_*B_*8*1024]; // kv matrices: [t,b,h][32 d][32 e]
__device__ float    g_wt[C_*C_];      // p_w transposed
__device__ __align__(16) __half g_wsplit[3][2][C_*C_]; // fp16 2-term split of q/k/v W

__device__ __forceinline__ uint32_t smem_u32(const void* p) {
    return (uint32_t)__cvta_generic_to_shared(p);
}
__device__ __forceinline__ void cp_async16(uint32_t saddr, const void* g) {
    asm volatile("cp.async.ca.shared.global [%0], [%1], 16;" :: "r"(saddr), "l"(g));
}

// ===========================================================================
// One-shot: 2-term fp16 split of q/k/v weights (x ~ h1 + h2 to ~2^-22)
// ===========================================================================
__global__ __launch_bounds__(256)
void wsplit_kernel(const float* __restrict__ qw, const float* __restrict__ kw,
                   const float* __restrict__ vw)
{
    int idx = blockIdx.x * 256 + threadIdx.x;         // < 3*65536
    int proj = idx >> 16, e = idx & 65535;
    const float* W = proj == 0 ? qw : (proj == 1 ? kw : vw);
    float x = W[e];
    __half h1 = __float2half_rn(x);
    __half h2 = __float2half_rn(x - __half2float(h1));
    g_wsplit[proj][0][e] = h1;
    g_wsplit[proj][1][e] = h2;
}

// ===========================================================================
// Pipelined WMMA projection GEMM + BN (fp32-accurate, 3-term fp16 split).
// One launch for q/k/v: blockIdx.z = tb*3 + proj. (unchanged from R9)
// ===========================================================================
#define KS 32
#define NSLAB 8
#define LDW2 40
#define LDX2 136
#define WBUF_BYTES (2*128*LDW2*2)                  // 20480
#define XS_OFF (2*WBUF_BYTES)                      // 40960
#define XS_BYTES (2*KS*LDX2*2)                     // 17408
#define SMEM_GT (128*132*4)                        // 67584

__global__ __launch_bounds__(256, 2)
void gemm_wmma_kernel(const float* __restrict__ X,
                      const float* __restrict__ qg, const float* __restrict__ qb,
                      const float* __restrict__ qm, const float* __restrict__ qv,
                      const float* __restrict__ kg, const float* __restrict__ kb,
                      const float* __restrict__ km, const float* __restrict__ kv,
                      const float* __restrict__ vg, const float* __restrict__ vb,
                      const float* __restrict__ vm, const float* __restrict__ vv)
{
    extern __shared__ __align__(16) char smem[];
    __half* Xs = (__half*)(smem + XS_OFF);
    float* stage = (float*)smem;

    const int tid = threadIdx.x, wid = tid >> 5;
    const int n0 = blockIdx.x * 128;
    const int m0 = blockIdx.y * 128;
    const int proj = blockIdx.z % 3;
    const int tb = blockIdx.z / 3;
    const float* Xb = X + (size_t)tb * CN_;
    float* Yb = g_y[proj] + (size_t)tb * CN_;

    const float* gamma = proj == 0 ? qg : (proj == 1 ? kg : vg);
    const float* beta  = proj == 0 ? qb : (proj == 1 ? kb : vb);
    const float* mean  = proj == 0 ? qm : (proj == 1 ? km : vm);
    const float* var   = proj == 0 ? qv : (proj == 1 ? kv : vv);

    const int wo = wid & 3;
    const int wn = wid >> 2;

    const uint32_t ws_base = smem_u32(smem);
    const int xr_r = tid >> 5;
    const int xr_v = tid & 31;

    wmma::fragment<wmma::accumulator, 16, 16, 16, float> acc[2][4];
    #pragma unroll
    for (int i = 0; i < 2; i++)
        #pragma unroll
        for (int j = 0; j < 4; j++) wmma::fill_fragment(acc[i][j], 0.0f);

    #pragma unroll
    for (int p = 0; p < 4; p++) {
        int ch = p * 256 + tid;
        int t = ch >> 9, r = (ch >> 2) & 127, v = ch & 3;
        cp_async16(ws_base + (uint32_t)((t * 128 + r) * LDW2 * 2 + v * 16),
                   g_wsplit[proj][t] + (m0 + r) * 256 + v * 8);
    }
    asm volatile("cp.async.commit_group;");
    float4 xr[4];
    #pragma unroll
    for (int p = 0; p < 4; p++)
        xr[p] = *(const float4*)(Xb + (size_t)(xr_r + p * 8) * N_ + n0 + xr_v * 4);

    for (int s = 0; s < NSLAB; s++) {
        const int buf = s & 1;

        #pragma unroll
        for (int p = 0; p < 4; p++) {
            int r = xr_r + p * 8;
            float xin[4] = {xr[p].x, xr[p].y, xr[p].z, xr[p].w};
            __half t1[4], t2[4];
            #pragma unroll
            for (int j = 0; j < 4; j++) {
                t1[j] = __float2half_rn(xin[j]);
                t2[j] = __float2half_rn(xin[j] - __half2float(t1[j]));
            }
            *(uint2*)(Xs + 0 * KS * LDX2 + r * LDX2 + xr_v * 4) = *(uint2*)t1;
            *(uint2*)(Xs + 1 * KS * LDX2 + r * LDX2 + xr_v * 4) = *(uint2*)t2;
        }

        if (s < NSLAB - 1) {
            uint32_t wb = ws_base + (uint32_t)((buf ^ 1) * WBUF_BYTES);
            #pragma unroll
            for (int p = 0; p < 4; p++) {
                int ch = p * 256 + tid;
                int t = ch >> 9, r = (ch >> 2) & 127, v = ch & 3;
                cp_async16(wb + (uint32_t)((t * 128 + r) * LDW2 * 2 + v * 16),
                           g_wsplit[proj][t] + (m0 + r) * 256 + (s + 1) * KS + v * 8);
            }
            asm volatile("cp.async.commit_group;");
            #pragma unroll
            for (int p = 0; p < 4; p++)
                xr[p] = *(const float4*)(Xb + (size_t)((s + 1) * KS + xr_r + p * 8) * N_ + n0 + xr_v * 4);
            asm volatile("cp.async.wait_group 1;");
        } else {
            asm volatile("cp.async.wait_group 0;");
        }
        __syncthreads();

        const __half* Wb = (const __half*)(smem + buf * WBUF_BYTES);
        #pragma unroll
        for (int ks = 0; ks < 2; ks++) {
            wmma::fragment<wmma::matrix_a, 16, 16, 16, __half, wmma::row_major> af[2][2];
            #pragma unroll
            for (int io = 0; io < 2; io++)
                #pragma unroll
                for (int t = 0; t < 2; t++)
                    wmma::load_matrix_sync(af[io][t],
                        Wb + t * 128 * LDW2 + (wo * 32 + io * 16) * LDW2 + ks * 16, LDW2);
            #pragma unroll
            for (int jn = 0; jn < 4; jn++) {
                wmma::fragment<wmma::matrix_b, 16, 16, 16, __half, wmma::row_major> bf[2];
                #pragma unroll
                for (int t = 0; t < 2; t++)
                    wmma::load_matrix_sync(bf[t],
                        Xs + t * KS * LDX2 + ks * 16 * LDX2 + wn * 64 + jn * 16, LDX2);
                #pragma unroll
                for (int io = 0; io < 2; io++) {
                    wmma::mma_sync(acc[io][jn], af[io][0], bf[0], acc[io][jn]);
                    wmma::mma_sync(acc[io][jn], af[io][1], bf[0], acc[io][jn]);
                    wmma::mma_sync(acc[io][jn], af[io][0], bf[1], acc[io][jn]);
                }
            }
        }
        __syncthreads();
    }

    #pragma unroll
    for (int io = 0; io < 2; io++)
        #pragma unroll
        for (int jn = 0; jn < 4; jn++)
            wmma::store_matrix_sync(stage + (wo * 32 + io * 16) * 132 + wn * 64 + jn * 16,
                                    acc[io][jn], 132, wmma::mem_row_major);
    __syncthreads();

    #pragma unroll
    for (int p = 0; p < 16; p++) {
        int idx = p * 256 + tid;
        int row = idx >> 5, c4 = (idx & 31) * 4;
        int o = m0 + row;
        float sc = gamma[o] * rsqrtf(var[o] + 1e-5f);
        float sh = beta[o] - mean[o] * sc;
        const float* sp = stage + row * 132 + c4;
        float4 yv = make_float4(sp[0] * sc + sh, sp[1] * sc + sh,
                                sp[2] * sc + sh, sp[3] * sc + sh);
        *(float4*)(Yb + (size_t)o * N_ + n0 + c4) = yv;
    }
}

// ===========================================================================
// LIF over T (vth=1) + bitpack for q,k,v. One thread per (b,h,n): 1536 blocks.
// ===========================================================================
__global__ __launch_bounds__(256)
void lif_pack_kernel()
{
    const int proj = blockIdx.y;
    const int idx = blockIdx.x * 256 + threadIdx.x;  // < B*8*N = 131072
    const int n = idx & (N_ - 1);
    const int h = (idx >> 10) & 7;
    const int b = idx >> 13;
    const float* Y = g_y[proj];

    unsigned bits[4] = {0u, 0u, 0u, 0u};
    for (int d = 0; d < 32; d++) {
        const float* p = Y + (size_t)b * CN_ + (size_t)(h * 32 + d) * N_ + n;
        float mem = 0.f;
        #pragma unroll
        for (int t = 0; t < 4; t++) {
            float y = p[(size_t)t * BCN];
            mem += (y - mem) * 0.5f;
            if (mem >= 1.0f) { bits[t] |= (1u << d); mem = 0.f; }
        }
    }
    const int ob = (b * 8 + h) * N_ + n;
    #pragma unroll
    for (int t = 0; t < 4; t++)
        g_bits[proj][t * (B_ * 8 * N_) + ob] = bits[t];
}

// ===========================================================================
// Write v output: fully coalesced linear unpack of g_bits[2].
// ===========================================================================
__global__ __launch_bounds__(256)
void v_writer_kernel(float* __restrict__ vout)
{
    const int idx = blockIdx.x * 256 + threadIdx.x;
    unsigned w = g_bits[2][idx >> 5];
    vout[idx] = (float)((w >> (idx & 31)) & 1u);
}

// ===========================================================================
// Per (t,b,h): kv[d][e] = popc over n of k_d & v_e -> g_kvm (2 MB).
// ===========================================================================
__global__ __launch_bounds__(256)
void kv_only_kernel()
{
    __shared__ unsigned kb[1024], vb[1024];
    __shared__ unsigned krow[32][33], vrow[32][33];

    const int bid = blockIdx.x;    // (t*B+b)*8+h
    const int tid = threadIdx.x;
    const unsigned base = (unsigned)bid * 1024u;

    for (int i = tid; i < 1024; i += 256) {
        kb[i] = g_bits[1][base + i];
        vb[i] = g_bits[2][base + i];
    }
    __syncthreads();

    const int d = tid & 31;
    for (int w = tid >> 5; w < 32; w += 8) {
        unsigned rk = 0u, rv = 0u;
        #pragma unroll
        for (int j = 0; j < 32; j++) {
            rk |= ((kb[w * 32 + j] >> d) & 1u) << j;
            rv |= ((vb[w * 32 + j] >> d) & 1u) << j;
        }
        krow[d][w] = rk; vrow[d][w] = rv;
    }
    __syncthreads();

    for (int p = tid; p < 1024; p += 256) {
        int dd = p >> 5, e = p & 31;
        int s = 0;
        #pragma unroll
        for (int w = 0; w < 32; w++)
            s += __popc(krow[dd][w] & vrow[e][w]);
        g_kvm[base + p] = (float)s;
    }
}

// ===========================================================================
// attn-apply + LIF(0.5) + xs bitpack, g_xa eliminated.
// Block = (n-chunk 256, h, b); thread = n; mem[32] in registers across t.
// y[e] = 0.125 * sum_{d in qm} kvm[d][e] (same ascending-d order as before).
// qm==0 fast path: mem *= 0.5 can never reach vth (post-step mem < 0.5).
// ===========================================================================
__global__ __launch_bounds__(256)
void attn_lif_kernel()
{
    __shared__ float kvm[4][32][33];

    const int n0 = blockIdx.x * 256;
    const int h  = blockIdx.y;
    const int b  = blockIdx.z;
    const int tid = threadIdx.x;

    for (int i = tid; i < 4096; i += 256) {
        int t = i >> 10, p = i & 1023;
        kvm[t][p >> 5][p & 31] = g_kvm[(size_t)((t * B_ + b) * 8 + h) * 1024 + p];
    }
    __syncthreads();

    float mem[32];
    #pragma unroll
    for (int e = 0; e < 32; e++) mem[e] = 0.f;

    const int ob = (b * 8 + h) * N_ + n0 + tid;
    #pragma unroll
    for (int t = 0; t < 4; t++) {
        unsigned qm = g_bits[0][t * (B_ * 8 * N_) + ob];
        unsigned bitsout = 0u;
        if (qm) {
            #pragma unroll
            for (int e = 0; e < 32; e++) {
                float s = 0.f;
                #pragma unroll
                for (int d = 0; d < 32; d++)
                    if (qm & (1u << d)) s += kvm[t][d][e];
                float y = 0.125f * s;
                mem[e] += (y - mem[e]) * 0.5f;
                if (mem[e] >= 0.5f) { bitsout |= (1u << e); mem[e] = 0.f; }
            }
        } else {
            #pragma unroll
            for (int e = 0; e < 32; e++) mem[e] *= 0.5f;
        }
        g_bits[3][t * (B_ * 8 * N_) + ob] = bitsout;
    }
}

__global__ __launch_bounds__(256)
void wt_kernel(const float* __restrict__ pw)
{
    int idx = blockIdx.x * 256 + threadIdx.x;
    int o = idx & 255, c = idx >> 8;
    g_wt[c * 256 + o] = pw[o * 256 + c];
}

// ===========================================================================
// Fused sparse p-GEMM + bias + BN + LIF(1.0) -> out (unchanged)
// ===========================================================================
__global__ __launch_bounds__(256)
void sparse_p_out_kernel(const float* __restrict__ pb,
                         const float* __restrict__ pg,
                         const float* __restrict__ pbt,
                         const float* __restrict__ pm,
                         const float* __restrict__ pv,
                         float* __restrict__ out)
{
    __shared__ unsigned mw[4][8][64];
    __shared__ unsigned fl[4][64];
    __shared__ float s_sc[256], s_sh[256], s_bi[256];

    const int n0 = blockIdx.x * 64;
    const int b  = blockIdx.y;
    const int tid = threadIdx.x;

    {
        float sc = pg[tid] * rsqrtf(pv[tid] + 1e-5f);
        s_sc[tid] = sc;
        s_sh[tid] = pbt[tid] - pm[tid] * sc;
        s_bi[tid] = pb[tid];
    }
    for (int i = tid; i < 2048; i += 256) {
        int nn = i & 63, w = (i >> 6) & 7, t = i >> 9;
        mw[t][w][nn] = g_bits[3][t * (B_ * 8 * N_) + (b * 8 + w) * N_ + n0 + nn];
    }
    __syncthreads();
    {
        int t = tid >> 6, nn = tid & 63;
        unsigned f = 0;
        #pragma unroll
        for (int w = 0; w < 8; w++) f |= mw[t][w][nn];
        fl[t][nn] = f;
    }
    __syncthreads();

    const int wi = tid >> 5, lane = tid & 31;
    for (int og = 0; og < 32; og++) {
        int o = og * 8 + wi;
        float sc = s_sc[o], sh = s_sh[o], bi = s_bi[o];
        float v0 = bi * sc + sh;
        #pragma unroll
        for (int nn2 = 0; nn2 < 2; nn2++) {
            int nn = nn2 * 32 + lane;
            float mem = 0.f;
            #pragma unroll
            for (int t = 0; t < 4; t++) {
                float y = v0;
                if (fl[t][nn]) {
                    float acc = 0.f;
                    #pragma unroll 1
                    for (int w = 0; w < 8; w++) {
                        unsigned m = mw[t][w][nn];
                        while (m) {
                            int d = __ffs(m) - 1;
                            m &= m - 1;
                            acc += g_wt[(w * 32 + d) * 256 + o];
                        }
                    }
                    y = (acc + bi) * sc + sh;
                }
                mem += (y - mem) * 0.5f;
                float s = (mem >= 1.0f) ? 1.0f : 0.0f;
                out[(size_t)t * BCN + (size_t)b * CN_ + (size_t)o * N_ + n0 + nn] = s;
                mem *= (1.0f - s);
            }
        }
    }
}

// ===========================================================================
extern "C" void kernel_launch(void* const* d_in, const int* in_sizes, int n_in,
                              void* d_out, int out_size)
{
    const float* x  = (const float*)d_in[0];
    const float* qw = (const float*)d_in[2];
    const float* qg = (const float*)d_in[3];
    const float* qb = (const float*)d_in[4];
    const float* qm = (const float*)d_in[5];
    const float* qv = (const float*)d_in[6];
    const float* kw = (const float*)d_in[7];
    const float* kg = (const float*)d_in[8];
    const float* kb = (const float*)d_in[9];
    const float* km = (const float*)d_in[10];
    const float* kv = (const float*)d_in[11];
    const float* vw = (const float*)d_in[12];
    const float* vg = (const float*)d_in[13];
    const float* vb = (const float*)d_in[14];
    const float* vm = (const float*)d_in[15];
    const float* vv = (const float*)d_in[16];
    const float* pw = (const float*)d_in[17];
    const float* pb = (const float*)d_in[18];
    const float* pg = (const float*)d_in[19];
    const float* pbt = (const float*)d_in[20];
    const float* pm = (const float*)d_in[21];
    const float* pv = (const float*)d_in[22];

    float* out  = (float*)d_out;
    float* vout = (out_size >= 2 * TBCN) ? out + TBCN : nullptr;

    static int smem_set = 0;
    if (!smem_set) {
        cudaFuncSetAttribute(gemm_wmma_kernel,
                             cudaFuncAttributeMaxDynamicSharedMemorySize, SMEM_GT);
        smem_set = 1;
    }

    // one-shot weight preps
    wsplit_kernel<<<3 * C_ * C_ / 256, 256>>>(qw, kw, vw);
    wt_kernel<<<C_ * C_ / 256, 256>>>(pw);

    // q,k,v projections fused into one pipelined wmma launch (fp16 3-term)
    dim3 tgrid(N_ / 128, C_ / 128, T_ * B_ * 3);
    gemm_wmma_kernel<<<tgrid, 256, SMEM_GT>>>(x, qg, qb, qm, qv,
                                              kg, kb, km, kv, vg, vb, vm, vv);

    // LIF(1.0) + bitpack for q,k,v (scalar, high-occupancy)
    lif_pack_kernel<<<dim3((B_ * 8 * N_) / 256, 3), 256>>>();

    // v output (coalesced)
    if (vout)
        v_writer_kernel<<<TBCN / 256, 256>>>(vout);

    // kv matrices -> g_kvm
    kv_only_kernel<<<T_ * B_ * 8, 256>>>();

    // attn-apply + LIF(0.5) + xs bitpack (no g_xa)
    attn_lif_kernel<<<dim3(N_ / 256, 8, B_), 256>>>();

    // fused sparse p-GEMM + BN + LIF(1.0) -> out
    sparse_p_out_kernel<<<dim3(N_ / 64, B_), 256>>>(pb, pg, pbt, pm, pv, out);
}